// round 1
// baseline (speedup 1.0000x reference)
#include <cuda_runtime.h>
#include <math.h>

// ---------------------------------------------------------------------------
// FractalBlock: 2-level recursive transformer block, B=4 N=1024 DIM=768
// Outputs: out [4,1024,768], attn0 [4,12,1024,1024], attn1 [4,12,1024,1024]
// Round 0: correct fp32 baseline. All GEMMs tiled 64x64x16, 4x4 microtile.
// ---------------------------------------------------------------------------

#define B_    4
#define NSEQ  1024
#define DIM_  768
#define HEADS 12
#define HDIM  64
#define MLPH  3072
#define MROWS (B_ * NSEQ)           // 4096
#define OUT_ELEMS   (MROWS * DIM_)  // 3145728
#define ATTN_ELEMS  (B_ * HEADS * NSEQ * NSEQ) // 50331648

// Scratch (device globals; no allocations allowed)
__device__ float g_ln [MROWS * DIM_];
__device__ float g_qkv[MROWS * 3 * DIM_];
__device__ float g_ao [MROWS * DIM_];
__device__ float g_h  [MROWS * MLPH];
__device__ float g_x1 [MROWS * DIM_];
__device__ float g_x2 [MROWS * DIM_];
__device__ float g_x3 [MROWS * DIM_];

__device__ __forceinline__ float gelu_exact(float x) {
    return 0.5f * x * (1.0f + erff(x * 0.70710678118654752f));
}

// ---------------------------------------------------------------------------
// LayerNorm: one block per row of 768
// ---------------------------------------------------------------------------
__global__ void ln_kernel(const float* __restrict__ x, const float* __restrict__ g,
                          const float* __restrict__ beta, float* __restrict__ y) {
    int row = blockIdx.x, t = threadIdx.x;
    const float* xr = x + (size_t)row * DIM_;
    float v0 = xr[t], v1 = xr[t + 256], v2 = xr[t + 512];
    float s = v0 + v1 + v2;
    float q = v0 * v0 + v1 * v1 + v2 * v2;
    __shared__ float rs[8], rq[8];
    #pragma unroll
    for (int o = 16; o; o >>= 1) {
        s += __shfl_xor_sync(0xffffffffu, s, o);
        q += __shfl_xor_sync(0xffffffffu, q, o);
    }
    int lane = t & 31, w = t >> 5;
    if (!lane) { rs[w] = s; rq[w] = q; }
    __syncthreads();
    float S = 0.f, Q = 0.f;
    #pragma unroll
    for (int i = 0; i < 8; ++i) { S += rs[i]; Q += rq[i]; }
    float mean = S * (1.0f / DIM_);
    float var  = Q * (1.0f / DIM_) - mean * mean;
    float inv  = rsqrtf(var + 1e-5f);
    float* yr = y + (size_t)row * DIM_;
    yr[t]       = (v0 - mean) * inv * g[t]       + beta[t];
    yr[t + 256] = (v1 - mean) * inv * g[t + 256] + beta[t + 256];
    yr[t + 512] = (v2 - mean) * inv * g[t + 512] + beta[t + 512];
}

// ---------------------------------------------------------------------------
// Generic GEMM: C[M,N] = A[M,K] @ W[K,N] + bias  (+ residual | gelu)
// BM=BN=64, BK=16, 256 threads, 4x4 microtile
// EPI: 0 = bias, 1 = bias+residual, 2 = bias+gelu
// ---------------------------------------------------------------------------
#define BM 64
#define BN 64
#define BK 16

template<int EPI>
__global__ void gemm_kernel(const float* __restrict__ A, const float* __restrict__ W,
                            const float* __restrict__ bias, const float* __restrict__ R,
                            float* __restrict__ C, int M, int N, int K) {
    __shared__ float As[BK][BM];       // [k][m]
    __shared__ float Bs[BK][BN + 4];   // [k][n], padded
    int t = threadIdx.x;
    int tx = t & 15, ty = t >> 4;
    int m0 = blockIdx.y * BM, n0 = blockIdx.x * BN;

    int arow = t >> 2, ak = (t & 3) * 4;       // A: 64 rows x 16 k
    int brow = t >> 4, bc = (t & 15) * 4;      // W: 16 k x 64 n
    const float* Aptr = A + (size_t)(m0 + arow) * K + ak;
    const float* Wptr = W + (size_t)brow * N + n0 + bc;

    float acc[4][4] = {};
    for (int k0 = 0; k0 < K; k0 += BK) {
        float4 a = *(const float4*)(Aptr + k0);
        As[ak + 0][arow] = a.x; As[ak + 1][arow] = a.y;
        As[ak + 2][arow] = a.z; As[ak + 3][arow] = a.w;
        *(float4*)&Bs[brow][bc] = *(const float4*)(Wptr + (size_t)k0 * N);
        __syncthreads();
        #pragma unroll
        for (int k = 0; k < BK; ++k) {
            float4 a4 = *(const float4*)&As[k][ty * 4];
            float4 b4 = *(const float4*)&Bs[k][tx * 4];
            float ar[4] = {a4.x, a4.y, a4.z, a4.w};
            float br[4] = {b4.x, b4.y, b4.z, b4.w};
            #pragma unroll
            for (int i = 0; i < 4; ++i)
                #pragma unroll
                for (int j = 0; j < 4; ++j)
                    acc[i][j] = fmaf(ar[i], br[j], acc[i][j]);
        }
        __syncthreads();
    }

    float4 bz = *(const float4*)&bias[n0 + tx * 4];
    float bb[4] = {bz.x, bz.y, bz.z, bz.w};
    #pragma unroll
    for (int i = 0; i < 4; ++i) {
        size_t idx = (size_t)(m0 + ty * 4 + i) * N + n0 + tx * 4;
        float vv[4];
        #pragma unroll
        for (int j = 0; j < 4; ++j) vv[j] = acc[i][j] + bb[j];
        if (EPI == 1) {
            float4 r = *(const float4*)&R[idx];
            vv[0] += r.x; vv[1] += r.y; vv[2] += r.z; vv[3] += r.w;
        }
        if (EPI == 2) {
            #pragma unroll
            for (int j = 0; j < 4; ++j) vv[j] = gelu_exact(vv[j]);
        }
        float4 o = {vv[0], vv[1], vv[2], vv[3]};
        *(float4*)&C[idx] = o;
    }
}

// ---------------------------------------------------------------------------
// Attention scores: S[bh, n, m] = scale * Q[bh,n,:] . K[bh,m,:]
// Q,K slices of qkv [4096, 2304]. Grid (16 mtiles(cols), 16 ntiles(rows), 48 bh)
// ---------------------------------------------------------------------------
__global__ void attn_scores_kernel(const float* __restrict__ qkv, float* __restrict__ S) {
    __shared__ float Qs[64][68];   // [d][row]
    __shared__ float Ks[64][68];   // [d][col]
    int t = threadIdx.x;
    int bh = blockIdx.z, b = bh / HEADS, h = bh % HEADS;
    int m0 = blockIdx.y * 64;      // q-row tile
    int n0 = blockIdx.x * 64;      // k-col tile
    const float* Qb = qkv + ((size_t)b * NSEQ) * (3 * DIM_) + h * HDIM;
    const float* Kb = Qb + DIM_;

    int r = t >> 2, c0 = (t & 3) * 16;
    const float* qrow = Qb + (size_t)(m0 + r) * (3 * DIM_) + c0;
    const float* krow = Kb + (size_t)(n0 + r) * (3 * DIM_) + c0;
    #pragma unroll
    for (int u = 0; u < 4; ++u) {
        float4 q = *(const float4*)(qrow + 4 * u);
        Qs[c0 + 4*u + 0][r] = q.x; Qs[c0 + 4*u + 1][r] = q.y;
        Qs[c0 + 4*u + 2][r] = q.z; Qs[c0 + 4*u + 3][r] = q.w;
        float4 k = *(const float4*)(krow + 4 * u);
        Ks[c0 + 4*u + 0][r] = k.x; Ks[c0 + 4*u + 1][r] = k.y;
        Ks[c0 + 4*u + 2][r] = k.z; Ks[c0 + 4*u + 3][r] = k.w;
    }
    __syncthreads();

    int tx = t & 15, ty = t >> 4;
    float acc[4][4] = {};
    #pragma unroll
    for (int k = 0; k < 64; ++k) {
        float4 a4 = *(const float4*)&Qs[k][ty * 4];
        float4 b4 = *(const float4*)&Ks[k][tx * 4];
        float ar[4] = {a4.x, a4.y, a4.z, a4.w};
        float br[4] = {b4.x, b4.y, b4.z, b4.w};
        #pragma unroll
        for (int i = 0; i < 4; ++i)
            #pragma unroll
            for (int j = 0; j < 4; ++j)
                acc[i][j] = fmaf(ar[i], br[j], acc[i][j]);
    }
    const float scale = 0.125f;   // 64^-0.5
    #pragma unroll
    for (int i = 0; i < 4; ++i) {
        size_t idx = ((size_t)bh * NSEQ + m0 + ty * 4 + i) * NSEQ + n0 + tx * 4;
        float4 o = {acc[i][0] * scale, acc[i][1] * scale,
                    acc[i][2] * scale, acc[i][3] * scale};
        *(float4*)&S[idx] = o;
    }
}

// ---------------------------------------------------------------------------
// Row softmax over 1024 elems, in place. One block (256 thr) per row.
// ---------------------------------------------------------------------------
__global__ void softmax_kernel(float* __restrict__ S) {
    size_t row = blockIdx.x;
    float4* p = (float4*)(S + row * NSEQ) + threadIdx.x;
    float4 v = *p;
    int t = threadIdx.x, lane = t & 31, w = t >> 5;
    __shared__ float red[8];

    float m = fmaxf(fmaxf(v.x, v.y), fmaxf(v.z, v.w));
    #pragma unroll
    for (int o = 16; o; o >>= 1) m = fmaxf(m, __shfl_xor_sync(0xffffffffu, m, o));
    if (!lane) red[w] = m;
    __syncthreads();
    float bm = red[0];
    #pragma unroll
    for (int i = 1; i < 8; ++i) bm = fmaxf(bm, red[i]);

    v.x = __expf(v.x - bm); v.y = __expf(v.y - bm);
    v.z = __expf(v.z - bm); v.w = __expf(v.w - bm);
    float s = v.x + v.y + v.z + v.w;
    #pragma unroll
    for (int o = 16; o; o >>= 1) s += __shfl_xor_sync(0xffffffffu, s, o);
    __syncthreads();
    if (!lane) red[w] = s;
    __syncthreads();
    float tot = 0.f;
    #pragma unroll
    for (int i = 0; i < 8; ++i) tot += red[i];
    float inv = 1.0f / tot;
    v.x *= inv; v.y *= inv; v.z *= inv; v.w *= inv;
    *p = v;
}

// ---------------------------------------------------------------------------
// PV: O[bh,n,d] = sum_m P[bh,n,m] * V[bh,m,d]; writes [B,N,H*hd] layout
// Grid (16 mtiles, 48 bh). BK=32.
// ---------------------------------------------------------------------------
__global__ void attn_pv_kernel(const float* __restrict__ S, const float* __restrict__ qkv,
                               float* __restrict__ O) {
    __shared__ float Ps[32][68];   // [k][m]
    __shared__ float Vs[32][68];   // [k][d]
    int t = threadIdx.x;
    int bh = blockIdx.y, b = bh / HEADS, h = bh % HEADS;
    int m0 = blockIdx.x * 64;
    const float* Pb = S + (size_t)bh * NSEQ * NSEQ;
    const float* Vb = qkv + ((size_t)b * NSEQ) * (3 * DIM_) + 2 * DIM_ + h * HDIM;

    int pr = t >> 2, pc = (t & 3) * 8;     // P: 64 rows x 32 k
    int vr = t >> 3, vc = (t & 7) * 8;     // V: 32 k x 64 d
    int tx = t & 15, ty = t >> 4;
    float acc[4][4] = {};

    for (int k0 = 0; k0 < NSEQ; k0 += 32) {
        const float* prow = Pb + (size_t)(m0 + pr) * NSEQ + k0 + pc;
        float4 p0 = *(const float4*)(prow);
        float4 p1 = *(const float4*)(prow + 4);
        Ps[pc + 0][pr] = p0.x; Ps[pc + 1][pr] = p0.y;
        Ps[pc + 2][pr] = p0.z; Ps[pc + 3][pr] = p0.w;
        Ps[pc + 4][pr] = p1.x; Ps[pc + 5][pr] = p1.y;
        Ps[pc + 6][pr] = p1.z; Ps[pc + 7][pr] = p1.w;
        const float* vrow = Vb + (size_t)(k0 + vr) * (3 * DIM_) + vc;
        *(float4*)&Vs[vr][vc]     = *(const float4*)(vrow);
        *(float4*)&Vs[vr][vc + 4] = *(const float4*)(vrow + 4);
        __syncthreads();
        #pragma unroll
        for (int k = 0; k < 32; ++k) {
            float4 a4 = *(const float4*)&Ps[k][ty * 4];
            float4 b4 = *(const float4*)&Vs[k][tx * 4];
            float ar[4] = {a4.x, a4.y, a4.z, a4.w};
            float br[4] = {b4.x, b4.y, b4.z, b4.w};
            #pragma unroll
            for (int i = 0; i < 4; ++i)
                #pragma unroll
                for (int j = 0; j < 4; ++j)
                    acc[i][j] = fmaf(ar[i], br[j], acc[i][j]);
        }
        __syncthreads();
    }
    #pragma unroll
    for (int i = 0; i < 4; ++i) {
        size_t idx = ((size_t)b * NSEQ + m0 + ty * 4 + i) * DIM_ + h * HDIM + tx * 4;
        float4 o = {acc[i][0], acc[i][1], acc[i][2], acc[i][3]};
        *(float4*)&O[idx] = o;
    }
}

// ---------------------------------------------------------------------------
// Blend: y = 0.5*(a + b), float4
// ---------------------------------------------------------------------------
__global__ void blend_kernel(const float* __restrict__ a, const float* __restrict__ b,
                             float* __restrict__ y) {
    int i = blockIdx.x * blockDim.x + threadIdx.x;
    float4 av = ((const float4*)a)[i];
    float4 bv = ((const float4*)b)[i];
    float4 o = {0.5f * (av.x + bv.x), 0.5f * (av.y + bv.y),
                0.5f * (av.z + bv.z), 0.5f * (av.w + bv.w)};
    ((float4*)y)[i] = o;
}

// ---------------------------------------------------------------------------
// Host orchestration
// ---------------------------------------------------------------------------
extern "C" void kernel_launch(void* const* d_in, const int* in_sizes, int n_in,
                              void* d_out, int out_size) {
    (void)in_sizes; (void)n_in; (void)out_size;
    const float* x = (const float*)d_in[0];
    const float* prm[24];
    for (int i = 0; i < 24; ++i) prm[i] = (const float*)d_in[1 + i];
    // per-layer param index: 0 qkv_w, 1 qkv_b, 2 proj_w, 3 proj_b, 4 ln1_g,
    // 5 ln1_b, 6 ln2_g, 7 ln2_b, 8 mlp_w1, 9 mlp_b1, 10 mlp_w2, 11 mlp_b2

    float* out   = (float*)d_out;
    float* attn0 = out + OUT_ELEMS;
    float* attn1 = attn0 + ATTN_ELEMS;

    float *p_ln, *p_qkv, *p_ao, *p_h, *p_x1, *p_x2, *p_x3;
    cudaGetSymbolAddress((void**)&p_ln,  g_ln);
    cudaGetSymbolAddress((void**)&p_qkv, g_qkv);
    cudaGetSymbolAddress((void**)&p_ao,  g_ao);
    cudaGetSymbolAddress((void**)&p_h,   g_h);
    cudaGetSymbolAddress((void**)&p_x1,  g_x1);
    cudaGetSymbolAddress((void**)&p_x2,  g_x2);
    cudaGetSymbolAddress((void**)&p_x3,  g_x3);

    dim3 blk(256);

    auto attention = [&](int L, const float* xin, float* attnbuf, float* xout) {
        const float* const* p = prm + L * 12;
        ln_kernel<<<MROWS, blk>>>(xin, p[4], p[5], p_ln);
        gemm_kernel<0><<<dim3(3 * DIM_ / BN, MROWS / BM), blk>>>(
            p_ln, p[0], p[1], nullptr, p_qkv, MROWS, 3 * DIM_, DIM_);
        attn_scores_kernel<<<dim3(16, 16, 48), blk>>>(p_qkv, attnbuf);
        softmax_kernel<<<48 * NSEQ, blk>>>(attnbuf);
        attn_pv_kernel<<<dim3(16, 48), blk>>>(attnbuf, p_qkv, p_ao);
        gemm_kernel<1><<<dim3(DIM_ / BN, MROWS / BM), blk>>>(
            p_ao, p[2], p[3], xin, xout, MROWS, DIM_, DIM_);
    };
    auto mlp = [&](int L, const float* xin, float* xout) {
        const float* const* p = prm + L * 12;
        ln_kernel<<<MROWS, blk>>>(xin, p[6], p[7], p_ln);
        gemm_kernel<2><<<dim3(MLPH / BN, MROWS / BM), blk>>>(
            p_ln, p[8], p[9], nullptr, p_h, MROWS, MLPH, DIM_);
        gemm_kernel<1><<<dim3(DIM_ / BN, MROWS / BM), blk>>>(
            p_h, p[10], p[11], xin, xout, MROWS, DIM_, MLPH);
    };

    attention(0, x,    attn0, p_x1);   // x1 = x + attn0_out
    attention(1, p_x1, attn1, p_x2);   // x2 = x1 + attn1_out
    mlp(1, p_x2, p_x3);                // x3 = x2 + mlp1(ln2_1(x2))  (= x_sub)
    blend_kernel<<<OUT_ELEMS / 4 / 256, blk>>>(p_x1, p_x3, p_x2); // xb -> reuse x2
    mlp(0, p_x2, out);                 // out = xb + mlp0(ln2_0(xb))
}

// round 2
// speedup vs baseline: 3.3294x; 3.3294x over previous
#include <cuda_runtime.h>
#include <math.h>
#include <stdint.h>

// ---------------------------------------------------------------------------
// FractalBlock on B200: tf32 tensor-core implementation.
// out [4,1024,768], attn0/attn1 [4,12,1024,1024]
// ---------------------------------------------------------------------------

#define B_    4
#define NSEQ  1024
#define DIM_  768
#define HEADS 12
#define HDIM  64
#define MLPH  3072
#define MROWS (B_ * NSEQ)                       // 4096
#define OUT_ELEMS   (MROWS * DIM_)              // 3145728
#define ATTN_ELEMS  (B_ * HEADS * NSEQ * NSEQ)  // 50331648

// Scratch (device globals)
__device__ float g_ln [MROWS * DIM_];
__device__ float g_qkv[MROWS * 3 * DIM_];
__device__ float g_ao [MROWS * DIM_];
__device__ float g_h  [MROWS * MLPH];
__device__ float g_x1 [MROWS * DIM_];
__device__ float g_x2 [MROWS * DIM_];
__device__ float g_x3 [MROWS * DIM_];
// tf32-rounded weights: per layer qkv_w(1769472) proj_w(589824) w1(2359296) w2(2359296)
#define WL_STRIDE 7077888
__device__ float g_wc [2 * WL_STRIDE];

__device__ __forceinline__ float tf32r(float x) {
    uint32_t u; asm("cvt.rna.tf32.f32 %0, %1;" : "=r"(u) : "f"(x));
    return __uint_as_float(u);
}
__device__ __forceinline__ float gelu_exact(float x) {
    return 0.5f * x * (1.0f + erff(x * 0.70710678118654752f));
}
__device__ __forceinline__ void mma_tf32(float d[4], uint32_t a0, uint32_t a1,
                                         uint32_t a2, uint32_t a3,
                                         uint32_t b0, uint32_t b1) {
    asm volatile(
        "mma.sync.aligned.m16n8k8.row.col.f32.tf32.tf32.f32 "
        "{%0,%1,%2,%3},{%4,%5,%6,%7},{%8,%9},{%0,%1,%2,%3};"
        : "+f"(d[0]), "+f"(d[1]), "+f"(d[2]), "+f"(d[3])
        : "r"(a0), "r"(a1), "r"(a2), "r"(a3), "r"(b0), "r"(b1));
}
__device__ __forceinline__ uint32_t smem_u32(const void* p) {
    return (uint32_t)__cvta_generic_to_shared(p);
}
#define CP16(dst, src) asm volatile("cp.async.cg.shared.global [%0],[%1],16;" :: "r"(dst), "l"(src))
#define CP_COMMIT()    asm volatile("cp.async.commit_group;")
#define CP_WAIT1()     asm volatile("cp.async.wait_group 1;")
#define CP_WAIT0()     asm volatile("cp.async.wait_group 0;")

// ---------------------------------------------------------------------------
// Weight tf32 pre-round: one float4 per thread
// ---------------------------------------------------------------------------
__global__ void conv_w_kernel(const float* __restrict__ src, float* __restrict__ dst) {
    int i = blockIdx.x * 256 + threadIdx.x;
    float4 v = ((const float4*)src)[i];
    v.x = tf32r(v.x); v.y = tf32r(v.y); v.z = tf32r(v.z); v.w = tf32r(v.w);
    ((float4*)dst)[i] = v;
}

// ---------------------------------------------------------------------------
// LayerNorm (writes tf32-rounded output; only GEMMs consume it)
// ---------------------------------------------------------------------------
__global__ void ln_kernel(const float* __restrict__ x, const float* __restrict__ g,
                          const float* __restrict__ beta, float* __restrict__ y) {
    int row = blockIdx.x, t = threadIdx.x;
    const float* xr = x + (size_t)row * DIM_;
    float v0 = xr[t], v1 = xr[t + 256], v2 = xr[t + 512];
    float s = v0 + v1 + v2;
    float q = v0 * v0 + v1 * v1 + v2 * v2;
    __shared__ float rs[8], rq[8];
    #pragma unroll
    for (int o = 16; o; o >>= 1) {
        s += __shfl_xor_sync(0xffffffffu, s, o);
        q += __shfl_xor_sync(0xffffffffu, q, o);
    }
    int lane = t & 31, w = t >> 5;
    if (!lane) { rs[w] = s; rq[w] = q; }
    __syncthreads();
    float S = 0.f, Q = 0.f;
    #pragma unroll
    for (int i = 0; i < 8; ++i) { S += rs[i]; Q += rq[i]; }
    float mean = S * (1.0f / DIM_);
    float var  = Q * (1.0f / DIM_) - mean * mean;
    float inv  = rsqrtf(var + 1e-5f);
    float* yr = y + (size_t)row * DIM_;
    yr[t]       = tf32r((v0 - mean) * inv * g[t]       + beta[t]);
    yr[t + 256] = tf32r((v1 - mean) * inv * g[t + 256] + beta[t + 256]);
    yr[t + 512] = tf32r((v2 - mean) * inv * g[t + 512] + beta[t + 512]);
}

// ---------------------------------------------------------------------------
// tf32 GEMM: C[M,N] = A[M,K] @ W[K,N] + bias (+res | +gelu)
// 128x128x32, 256 thr (8 warps 2x4), cp.async double buffer.
// A and W must already be tf32-valued. EPI: 0=bias(round) 1=bias+res 2=bias+gelu(round)
// ---------------------------------------------------------------------------
#define GBM 128
#define GBN 128
#define GBK 32
#define AST 36
#define BST 136
#define GEMM_SMEM ((2*GBM*AST + 2*GBK*BST) * 4)

template<int EPI>
__global__ void gemm_tf32(const float* __restrict__ A, const float* __restrict__ W,
                          const float* __restrict__ bias, const float* __restrict__ R,
                          float* __restrict__ C, int M, int N, int K) {
    extern __shared__ float sm[];
    float* As = sm;                       // [2][GBM][AST]
    float* Bs = sm + 2 * GBM * AST;       // [2][GBK][BST]
    const int t = threadIdx.x;
    const int w = t >> 5, lane = t & 31, g = lane >> 2, c = lane & 3;
    const int wm = (w >> 2) * 64, wn = (w & 3) * 32;
    const int m0 = blockIdx.y * GBM, n0 = blockIdx.x * GBN;

    int am[4], ak[4], bk[4], bn[4];
    #pragma unroll
    for (int i = 0; i < 4; ++i) {
        int li = t + i * 256;
        am[i] = li >> 3; ak[i] = (li & 7) * 4;
        bk[i] = li >> 5; bn[i] = (li & 31) * 4;
    }

    const int NT = K / GBK;
    auto issue = [&](int kt, int buf) {
        const float* Ab = A + (size_t)m0 * K + kt * GBK;
        const float* Wb = W + (size_t)(kt * GBK) * N + n0;
        float* Asb = As + buf * GBM * AST;
        float* Bsb = Bs + buf * GBK * BST;
        #pragma unroll
        for (int i = 0; i < 4; ++i) {
            CP16(smem_u32(Asb + am[i] * AST + ak[i]), Ab + (size_t)am[i] * K + ak[i]);
            CP16(smem_u32(Bsb + bk[i] * BST + bn[i]), Wb + (size_t)bk[i] * N + bn[i]);
        }
        CP_COMMIT();
    };

    issue(0, 0);
    float acc[4][4][4] = {};
    for (int kt = 0; kt < NT; ++kt) {
        int buf = kt & 1;
        if (kt + 1 < NT) { issue(kt + 1, buf ^ 1); CP_WAIT1(); }
        else             { CP_WAIT0(); }
        __syncthreads();
        const float* Asb = As + buf * GBM * AST;
        const float* Bsb = Bs + buf * GBK * BST;
        #pragma unroll
        for (int ks = 0; ks < 4; ++ks) {
            const int k8 = ks * 8;
            uint32_t af[4][4], bf[4][2];
            #pragma unroll
            for (int mt = 0; mt < 4; ++mt) {
                const float* ap = Asb + (wm + mt * 16 + g) * AST + k8 + c;
                af[mt][0] = __float_as_uint(ap[0]);
                af[mt][1] = __float_as_uint(ap[8 * AST]);
                af[mt][2] = __float_as_uint(ap[4]);
                af[mt][3] = __float_as_uint(ap[8 * AST + 4]);
            }
            #pragma unroll
            for (int nt = 0; nt < 4; ++nt) {
                const float* bp = Bsb + (k8 + c) * BST + wn + nt * 8 + g;
                bf[nt][0] = __float_as_uint(bp[0]);
                bf[nt][1] = __float_as_uint(bp[4 * BST]);
            }
            #pragma unroll
            for (int mt = 0; mt < 4; ++mt)
                #pragma unroll
                for (int nt = 0; nt < 4; ++nt)
                    mma_tf32(acc[mt][nt], af[mt][0], af[mt][1], af[mt][2], af[mt][3],
                             bf[nt][0], bf[nt][1]);
        }
        __syncthreads();
    }

    #pragma unroll
    for (int mt = 0; mt < 4; ++mt) {
        #pragma unroll
        for (int nt = 0; nt < 4; ++nt) {
            int row = m0 + wm + mt * 16 + g;
            int col = n0 + wn + nt * 8 + 2 * c;
            float2 bb = *(const float2*)&bias[col];
            #pragma unroll
            for (int hh = 0; hh < 2; ++hh) {
                size_t idx = (size_t)(row + hh * 8) * N + col;
                float v0 = acc[mt][nt][hh * 2 + 0] + bb.x;
                float v1 = acc[mt][nt][hh * 2 + 1] + bb.y;
                if (EPI == 1) { float2 rr = *(const float2*)&R[idx]; v0 += rr.x; v1 += rr.y; }
                if (EPI == 2) { v0 = gelu_exact(v0); v1 = gelu_exact(v1); }
                if (EPI != 1) { v0 = tf32r(v0); v1 = tf32r(v1); }
                float2 o = {v0, v1};
                *(float2*)&C[idx] = o;
            }
        }
    }
}

// ---------------------------------------------------------------------------
// Fused attention scores + softmax.
// Block = 32 query rows x all 1024 keys for one (b,h). tf32 mma QK^T,
// streams K in 128-key double-buffered chunks, softmax in-register,
// single write of the attention map.
// ---------------------------------------------------------------------------
#define SMST 1032                    // Sm row stride (floats)
#define SC_SMEM ((32*SMST + 32*68 + 2*128*68) * 4)   // 210432 B

__global__ void attn_scores_softmax(const float* __restrict__ qkv, float* __restrict__ S) {
    extern __shared__ float sm[];
    float* Sm = sm;                     // [32][SMST]
    float* Qs = sm + 32 * SMST;         // [32][68]
    float* Ks = Qs + 32 * 68;           // [2][128][68]
    const int t = threadIdx.x;
    const int w = t >> 5, lane = t & 31, g = lane >> 2, c = lane & 3;
    const int bh = blockIdx.y, b = bh / HEADS, h = bh % HEADS;
    const int m0 = blockIdx.x * 32;
    const int wm = (w >> 2) * 16, wn = (w & 3) * 32;
    const float* Qb = qkv + ((size_t)b * NSEQ + m0) * (3 * DIM_) + h * HDIM;
    const float* Kb = qkv + ((size_t)b * NSEQ) * (3 * DIM_) + DIM_ + h * HDIM;

    // Q: 32x64 (already tf32-valued)
    #pragma unroll
    for (int i = 0; i < 2; ++i) {
        int li = t + i * 256;
        int r = li >> 4, q = (li & 15) * 4;
        *(float4*)&Qs[r * 68 + q] = *(const float4*)(Qb + (size_t)r * (3 * DIM_) + q);
    }

    auto issueK = [&](int ch, int buf) {
        float* Kd = Ks + buf * 128 * 68;
        const float* Kg = Kb + (size_t)(ch * 128) * (3 * DIM_);
        #pragma unroll
        for (int i = 0; i < 8; ++i) {
            int li = t + i * 256;
            int key = li >> 4, q = (li & 15) * 4;
            CP16(smem_u32(Kd + key * 68 + q), Kg + (size_t)key * (3 * DIM_) + q);
        }
        CP_COMMIT();
    };
    issueK(0, 0);
    __syncthreads();   // Qs visible

    uint32_t aq[8][4];
    #pragma unroll
    for (int ks = 0; ks < 8; ++ks) {
        const float* ap = Qs + (wm + g) * 68 + ks * 8 + c;
        aq[ks][0] = __float_as_uint(ap[0]);
        aq[ks][1] = __float_as_uint(ap[8 * 68]);
        aq[ks][2] = __float_as_uint(ap[4]);
        aq[ks][3] = __float_as_uint(ap[8 * 68 + 4]);
    }

    for (int ch = 0; ch < 8; ++ch) {
        int buf = ch & 1;
        if (ch + 1 < 8) { issueK(ch + 1, buf ^ 1); CP_WAIT1(); }
        else            { CP_WAIT0(); }
        __syncthreads();
        const float* Kc = Ks + buf * 128 * 68;
        float acc[4][4] = {};
        #pragma unroll
        for (int ks = 0; ks < 8; ++ks) {
            const int k8 = ks * 8;
            #pragma unroll
            for (int nt = 0; nt < 4; ++nt) {
                const float* bp = Kc + (wn + nt * 8 + g) * 68 + k8 + c;
                uint32_t b0 = __float_as_uint(bp[0]);
                uint32_t b1 = __float_as_uint(bp[4]);
                mma_tf32(acc[nt], aq[ks][0], aq[ks][1], aq[ks][2], aq[ks][3], b0, b1);
            }
        }
        const float scl = 0.125f;
        #pragma unroll
        for (int nt = 0; nt < 4; ++nt) {
            int colb = ch * 128 + wn + nt * 8 + 2 * c;
            int row = wm + g;
            float2 o0 = {acc[nt][0] * scl, acc[nt][1] * scl};
            float2 o1 = {acc[nt][2] * scl, acc[nt][3] * scl};
            *(float2*)&Sm[row * SMST + colb]       = o0;
            *(float2*)&Sm[(row + 8) * SMST + colb] = o1;
        }
        __syncthreads();
    }

    // Softmax: warp w owns rows w*4 .. w*4+3
    #pragma unroll
    for (int i = 0; i < 4; ++i) {
        int r = w * 4 + i;
        const float* rowp = Sm + r * SMST;
        float4 v[8];
        float mx = -INFINITY;
        #pragma unroll
        for (int j = 0; j < 8; ++j) {
            v[j] = *(const float4*)(rowp + lane * 4 + j * 128);
            mx = fmaxf(mx, fmaxf(fmaxf(v[j].x, v[j].y), fmaxf(v[j].z, v[j].w)));
        }
        #pragma unroll
        for (int o = 16; o; o >>= 1) mx = fmaxf(mx, __shfl_xor_sync(0xffffffffu, mx, o));
        float s = 0.f;
        #pragma unroll
        for (int j = 0; j < 8; ++j) {
            v[j].x = __expf(v[j].x - mx); v[j].y = __expf(v[j].y - mx);
            v[j].z = __expf(v[j].z - mx); v[j].w = __expf(v[j].w - mx);
            s += v[j].x + v[j].y + v[j].z + v[j].w;
        }
        #pragma unroll
        for (int o = 16; o; o >>= 1) s += __shfl_xor_sync(0xffffffffu, s, o);
        float inv = 1.0f / s;
        float* outp = S + ((size_t)bh * NSEQ + m0 + r) * NSEQ + lane * 4;
        #pragma unroll
        for (int j = 0; j < 8; ++j) {
            float4 o = {v[j].x * inv, v[j].y * inv, v[j].z * inv, v[j].w * inv};
            *(float4*)(outp + j * 128) = o;
        }
    }
}

// ---------------------------------------------------------------------------
// PV: O = P @ V per (b,h). 128x64 tile, K=1024 in 32-key double-buffered chunks.
// P is fp32 (converted per-fragment); V already tf32-valued.
// ---------------------------------------------------------------------------
#define PVST 72
#define PV_SMEM ((2*128*36 + 2*32*PVST) * 4)   // 55296 B

__global__ void attn_pv(const float* __restrict__ S, const float* __restrict__ qkv,
                        float* __restrict__ O) {
    extern __shared__ float sm[];
    float* Ps = sm;                     // [2][128][36]
    float* Vs = sm + 2 * 128 * 36;      // [2][32][PVST]
    const int t = threadIdx.x;
    const int w = t >> 5, lane = t & 31, g = lane >> 2, c = lane & 3;
    const int bh = blockIdx.y, b = bh / HEADS, h = bh % HEADS;
    const int m0 = blockIdx.x * 128;
    const int wm = (w >> 1) * 32, wn = (w & 1) * 32;
    const float* Pb = S + ((size_t)bh * NSEQ + m0) * NSEQ;
    const float* Vb = qkv + (size_t)b * NSEQ * (3 * DIM_) + 2 * DIM_ + h * HDIM;

    auto issue = [&](int kt, int buf) {
        float* Pd = Ps + buf * 128 * 36;
        float* Vd = Vs + buf * 32 * PVST;
        #pragma unroll
        for (int i = 0; i < 4; ++i) {
            int li = t + i * 256;
            int m = li >> 3, kq = (li & 7) * 4;
            CP16(smem_u32(Pd + m * 36 + kq), Pb + (size_t)m * NSEQ + kt * 32 + kq);
        }
        #pragma unroll
        for (int i = 0; i < 2; ++i) {
            int li = t + i * 256;
            int key = li >> 4, q = (li & 15) * 4;
            CP16(smem_u32(Vd + key * PVST + q),
                 Vb + (size_t)(kt * 32 + key) * (3 * DIM_) + q);
        }
        CP_COMMIT();
    };

    issue(0, 0);
    float acc[2][4][4] = {};
    for (int kt = 0; kt < 32; ++kt) {
        int buf = kt & 1;
        if (kt + 1 < 32) { issue(kt + 1, buf ^ 1); CP_WAIT1(); }
        else             { CP_WAIT0(); }
        __syncthreads();
        const float* Psb = Ps + buf * 128 * 36;
        const float* Vsb = Vs + buf * 32 * PVST;
        #pragma unroll
        for (int ks = 0; ks < 4; ++ks) {
            const int k8 = ks * 8;
            uint32_t af[2][4], bf[4][2];
            #pragma unroll
            for (int mt = 0; mt < 2; ++mt) {
                const float* ap = Psb + (wm + mt * 16 + g) * 36 + k8 + c;
                af[mt][0] = __float_as_uint(tf32r(ap[0]));
                af[mt][1] = __float_as_uint(tf32r(ap[8 * 36]));
                af[mt][2] = __float_as_uint(tf32r(ap[4]));
                af[mt][3] = __float_as_uint(tf32r(ap[8 * 36 + 4]));
            }
            #pragma unroll
            for (int nt = 0; nt < 4; ++nt) {
                const float* bp = Vsb + (k8 + c) * PVST + wn + nt * 8 + g;
                bf[nt][0] = __float_as_uint(bp[0]);
                bf[nt][1] = __float_as_uint(bp[4 * PVST]);
            }
            #pragma unroll
            for (int mt = 0; mt < 2; ++mt)
                #pragma unroll
                for (int nt = 0; nt < 4; ++nt)
                    mma_tf32(acc[mt][nt], af[mt][0], af[mt][1], af[mt][2], af[mt][3],
                             bf[nt][0], bf[nt][1]);
        }
        __syncthreads();
    }

    #pragma unroll
    for (int mt = 0; mt < 2; ++mt) {
        #pragma unroll
        for (int nt = 0; nt < 4; ++nt) {
            int row = m0 + wm + mt * 16 + g;
            int col = wn + nt * 8 + 2 * c;
            #pragma unroll
            for (int hh = 0; hh < 2; ++hh) {
                size_t idx = ((size_t)b * NSEQ + row + hh * 8) * DIM_ + h * HDIM + col;
                float2 o = {tf32r(acc[mt][nt][hh * 2 + 0]), tf32r(acc[mt][nt][hh * 2 + 1])};
                *(float2*)&O[idx] = o;
            }
        }
    }
}

// ---------------------------------------------------------------------------
// Blend: y = 0.5*(a+b)
// ---------------------------------------------------------------------------
__global__ void blend_kernel(const float* __restrict__ a, const float* __restrict__ b,
                             float* __restrict__ y) {
    int i = blockIdx.x * blockDim.x + threadIdx.x;
    float4 av = ((const float4*)a)[i];
    float4 bv = ((const float4*)b)[i];
    float4 o = {0.5f * (av.x + bv.x), 0.5f * (av.y + bv.y),
                0.5f * (av.z + bv.z), 0.5f * (av.w + bv.w)};
    ((float4*)y)[i] = o;
}

// ---------------------------------------------------------------------------
// Host orchestration
// ---------------------------------------------------------------------------
extern "C" void kernel_launch(void* const* d_in, const int* in_sizes, int n_in,
                              void* d_out, int out_size) {
    (void)in_sizes; (void)n_in; (void)out_size;
    const float* x = (const float*)d_in[0];
    const float* prm[24];
    for (int i = 0; i < 24; ++i) prm[i] = (const float*)d_in[1 + i];
    // per-layer: 0 qkv_w, 1 qkv_b, 2 proj_w, 3 proj_b, 4 ln1_g, 5 ln1_b,
    //            6 ln2_g, 7 ln2_b, 8 mlp_w1, 9 mlp_b1, 10 mlp_w2, 11 mlp_b2

    float* out   = (float*)d_out;
    float* attn0 = out + OUT_ELEMS;
    float* attn1 = attn0 + ATTN_ELEMS;

    float *p_ln, *p_qkv, *p_ao, *p_h, *p_x1, *p_x2, *p_x3, *p_wc;
    cudaGetSymbolAddress((void**)&p_ln,  g_ln);
    cudaGetSymbolAddress((void**)&p_qkv, g_qkv);
    cudaGetSymbolAddress((void**)&p_ao,  g_ao);
    cudaGetSymbolAddress((void**)&p_h,   g_h);
    cudaGetSymbolAddress((void**)&p_x1,  g_x1);
    cudaGetSymbolAddress((void**)&p_x2,  g_x2);
    cudaGetSymbolAddress((void**)&p_x3,  g_x3);
    cudaGetSymbolAddress((void**)&p_wc,  g_wc);

    cudaFuncSetAttribute(gemm_tf32<0>, cudaFuncAttributeMaxDynamicSharedMemorySize, GEMM_SMEM);
    cudaFuncSetAttribute(gemm_tf32<1>, cudaFuncAttributeMaxDynamicSharedMemorySize, GEMM_SMEM);
    cudaFuncSetAttribute(gemm_tf32<2>, cudaFuncAttributeMaxDynamicSharedMemorySize, GEMM_SMEM);
    cudaFuncSetAttribute(attn_scores_softmax, cudaFuncAttributeMaxDynamicSharedMemorySize, SC_SMEM);
    cudaFuncSetAttribute(attn_pv, cudaFuncAttributeMaxDynamicSharedMemorySize, PV_SMEM);

    dim3 blk(256);

    // tf32-round weights into scratch
    const int QKV_N = DIM_ * 3 * DIM_;   // 1769472
    const int PRJ_N = DIM_ * DIM_;       // 589824
    const int W1_N  = DIM_ * MLPH;       // 2359296
    const int W2_N  = MLPH * DIM_;       // 2359296
    float* wq[2]; float* wp[2]; float* w1[2]; float* w2[2];
    for (int L = 0; L < 2; ++L) {
        float* base = p_wc + (size_t)L * WL_STRIDE;
        wq[L] = base;
        wp[L] = base + QKV_N;
        w1[L] = base + QKV_N + PRJ_N;
        w2[L] = base + QKV_N + PRJ_N + W1_N;
        conv_w_kernel<<<QKV_N / 1024, blk>>>(prm[L*12 + 0],  wq[L]);
        conv_w_kernel<<<PRJ_N / 1024, blk>>>(prm[L*12 + 2],  wp[L]);
        conv_w_kernel<<<W1_N  / 1024, blk>>>(prm[L*12 + 8],  w1[L]);
        conv_w_kernel<<<W2_N  / 1024, blk>>>(prm[L*12 + 10], w2[L]);
    }

    auto attention = [&](int L, const float* xin, float* attnbuf, float* xout) {
        const float* const* p = prm + L * 12;
        ln_kernel<<<MROWS, blk>>>(xin, p[4], p[5], p_ln);
        gemm_tf32<0><<<dim3(3 * DIM_ / GBN, MROWS / GBM), blk, GEMM_SMEM>>>(
            p_ln, wq[L], p[1], nullptr, p_qkv, MROWS, 3 * DIM_, DIM_);
        attn_scores_softmax<<<dim3(32, 48), blk, SC_SMEM>>>(p_qkv, attnbuf);
        attn_pv<<<dim3(8, 48), blk, PV_SMEM>>>(attnbuf, p_qkv, p_ao);
        gemm_tf32<1><<<dim3(DIM_ / GBN, MROWS / GBM), blk, GEMM_SMEM>>>(
            p_ao, wp[L], p[3], xin, xout, MROWS, DIM_, DIM_);
    };
    auto mlp = [&](int L, const float* xin, float* xout) {
        const float* const* p = prm + L * 12;
        ln_kernel<<<MROWS, blk>>>(xin, p[6], p[7], p_ln);
        gemm_tf32<2><<<dim3(MLPH / GBN, MROWS / GBM), blk, GEMM_SMEM>>>(
            p_ln, w1[L], p[9], nullptr, p_h, MROWS, MLPH, DIM_);
        gemm_tf32<1><<<dim3(DIM_ / GBN, MROWS / GBM), blk, GEMM_SMEM>>>(
            p_h, w2[L], p[11], xin, xout, MROWS, DIM_, MLPH);
    };

    attention(0, x,    attn0, p_x1);
    attention(1, p_x1, attn1, p_x2);
    mlp(1, p_x2, p_x3);
    blend_kernel<<<OUT_ELEMS / 4 / 256, blk>>>(p_x1, p_x3, p_x2);
    mlp(0, p_x2, out);
}

// round 6
// speedup vs baseline: 4.5708x; 1.3729x over previous
#include <cuda_runtime.h>
#include <cuda_fp16.h>
#include <math.h>
#include <stdint.h>

// ---------------------------------------------------------------------------
// FractalBlock on B200 (compute_100 toolchain => no tcgen05).
// fp16 m16n8k16 mma.sync for all dense GEMMs + QK^T; tf32 mma for PV.
// out [4,1024,768] fp32, attn0/attn1 [4,12,1024,1024] fp32.
// ---------------------------------------------------------------------------

#define B_    4
#define NSEQ  1024
#define DIM_  768
#define HEADS 12
#define HDIM  64
#define MLPH  3072
#define MROWS (B_ * NSEQ)                       // 4096
#define OUT_ELEMS   (MROWS * DIM_)              // 3145728
#define ATTN_ELEMS  (B_ * HEADS * NSEQ * NSEQ)  // 50331648

// Scratch (device globals)
__device__ __half g_ln [MROWS * DIM_];
__device__ __half g_qkv[MROWS * 3 * DIM_];
__device__ __half g_ao [MROWS * DIM_];
__device__ __half g_h  [MROWS * MLPH];
__device__ float  g_x1 [MROWS * DIM_];
__device__ float  g_x2 [MROWS * DIM_];
__device__ float  g_x3 [MROWS * DIM_];
// transposed fp16 weights per layer: qkvT(2304x768) projT(768x768)
// w1T(3072x768) w2T(768x3072)
#define WL_STRIDE 7077888
__device__ __half g_wc [2 * WL_STRIDE];

__device__ __forceinline__ float tf32r(float x) {
    uint32_t u; asm("cvt.rna.tf32.f32 %0, %1;" : "=r"(u) : "f"(x));
    return __uint_as_float(u);
}
__device__ __forceinline__ float gelu_exact(float x) {
    return 0.5f * x * (1.0f + erff(x * 0.70710678118654752f));
}
// fp16 mma, f32 accumulate
__device__ __forceinline__ void mma_h(float d[4], uint32_t a0, uint32_t a1,
                                      uint32_t a2, uint32_t a3,
                                      uint32_t b0, uint32_t b1) {
    asm volatile(
        "mma.sync.aligned.m16n8k16.row.col.f32.f16.f16.f32 "
        "{%0,%1,%2,%3},{%4,%5,%6,%7},{%8,%9},{%0,%1,%2,%3};"
        : "+f"(d[0]), "+f"(d[1]), "+f"(d[2]), "+f"(d[3])
        : "r"(a0), "r"(a1), "r"(a2), "r"(a3), "r"(b0), "r"(b1));
}
// tf32 mma (PV only)
__device__ __forceinline__ void mma_tf32(float d[4], uint32_t a0, uint32_t a1,
                                         uint32_t a2, uint32_t a3,
                                         uint32_t b0, uint32_t b1) {
    asm volatile(
        "mma.sync.aligned.m16n8k8.row.col.f32.tf32.tf32.f32 "
        "{%0,%1,%2,%3},{%4,%5,%6,%7},{%8,%9},{%0,%1,%2,%3};"
        : "+f"(d[0]), "+f"(d[1]), "+f"(d[2]), "+f"(d[3])
        : "r"(a0), "r"(a1), "r"(a2), "r"(a3), "r"(b0), "r"(b1));
}
__device__ __forceinline__ uint32_t smem_u32(const void* p) {
    return (uint32_t)__cvta_generic_to_shared(p);
}
#define CP16(dst, src) asm volatile("cp.async.cg.shared.global [%0],[%1],16;" :: "r"(dst), "l"(src))
#define CP_COMMIT()    asm volatile("cp.async.commit_group;")
#define CP_WAIT1()     asm volatile("cp.async.wait_group 1;")
#define CP_WAIT0()     asm volatile("cp.async.wait_group 0;")

// ---------------------------------------------------------------------------
// Weight transpose + fp16 convert: dst[N,K] = h(src[K,N])
// ---------------------------------------------------------------------------
__global__ void transpose_w(const float* __restrict__ src, __half* __restrict__ dst,
                            int K, int N) {
    __shared__ float tl[32][33];
    int n0 = blockIdx.x * 32, k0 = blockIdx.y * 32;
    int tx = threadIdx.x, ty = threadIdx.y;
    #pragma unroll
    for (int j = 0; j < 4; ++j)
        tl[ty + 8 * j][tx] = src[(size_t)(k0 + ty + 8 * j) * N + n0 + tx];
    __syncthreads();
    #pragma unroll
    for (int j = 0; j < 4; ++j)
        dst[(size_t)(n0 + ty + 8 * j) * K + k0 + tx] = __float2half_rn(tl[tx][ty + 8 * j]);
}

// ---------------------------------------------------------------------------
// LayerNorm: fp32 in -> fp16 out
// ---------------------------------------------------------------------------
__global__ void ln_kernel(const float* __restrict__ x, const float* __restrict__ g,
                          const float* __restrict__ beta, __half* __restrict__ y) {
    int row = blockIdx.x, t = threadIdx.x;
    const float* xr = x + (size_t)row * DIM_;
    float v0 = xr[t], v1 = xr[t + 256], v2 = xr[t + 512];
    float s = v0 + v1 + v2;
    float q = v0 * v0 + v1 * v1 + v2 * v2;
    __shared__ float rs[8], rq[8];
    #pragma unroll
    for (int o = 16; o; o >>= 1) {
        s += __shfl_xor_sync(0xffffffffu, s, o);
        q += __shfl_xor_sync(0xffffffffu, q, o);
    }
    int lane = t & 31, w = t >> 5;
    if (!lane) { rs[w] = s; rq[w] = q; }
    __syncthreads();
    float S = 0.f, Q = 0.f;
    #pragma unroll
    for (int i = 0; i < 8; ++i) { S += rs[i]; Q += rq[i]; }
    float mean = S * (1.0f / DIM_);
    float var  = Q * (1.0f / DIM_) - mean * mean;
    float inv  = rsqrtf(var + 1e-5f);
    __half* yr = y + (size_t)row * DIM_;
    yr[t]       = __float2half_rn((v0 - mean) * inv * g[t]       + beta[t]);
    yr[t + 256] = __float2half_rn((v1 - mean) * inv * g[t + 256] + beta[t + 256]);
    yr[t + 512] = __float2half_rn((v2 - mean) * inv * g[t + 512] + beta[t + 512]);
}

// ---------------------------------------------------------------------------
// fp16 GEMM: C[M,N] = A[M,K] @ Wt[N,K]^T + bias (+res | +gelu)
// 128x128 tile, BK=32 halves, 256 thr (8 warps 2x4), double-buffered cp.async.
// EPI: 0 = bias -> half out; 1 = bias+residual -> fp32 out; 2 = bias+gelu -> half out
// ---------------------------------------------------------------------------
#define HST 40    // smem row stride in halves (80B: conflict-free fragments)

template<int EPI>
__global__ void __launch_bounds__(256)
gemm_h(const __half* __restrict__ A, const __half* __restrict__ Wt,
       const float* __restrict__ bias, const float* __restrict__ R,
       void* __restrict__ Cv, int M, int N, int K) {
    __shared__ __half As[2][128][HST];
    __shared__ __half Bs[2][128][HST];
    const int t = threadIdx.x;
    const int w = t >> 5, lane = t & 31, g = lane >> 2, c = lane & 3;
    const int wm = (w >> 2) * 64, wn = (w & 3) * 32;
    const int m0 = blockIdx.y * 128, n0 = blockIdx.x * 128;
    const int NT = K / 32;

    auto issue = [&](int kt, int buf) {
        #pragma unroll
        for (int i = 0; i < 2; ++i) {
            int li = t + i * 256;
            int row = li >> 2, ch = li & 3;
            CP16(smem_u32(&As[buf][row][ch * 8]),
                 A + (size_t)(m0 + row) * K + kt * 32 + ch * 8);
            CP16(smem_u32(&Bs[buf][row][ch * 8]),
                 Wt + (size_t)(n0 + row) * K + kt * 32 + ch * 8);
        }
        CP_COMMIT();
    };

    issue(0, 0);
    float acc[4][4][4] = {};
    for (int kt = 0; kt < NT; ++kt) {
        int buf = kt & 1;
        if (kt + 1 < NT) { issue(kt + 1, buf ^ 1); CP_WAIT1(); }
        else             { CP_WAIT0(); }
        __syncthreads();
        #pragma unroll
        for (int ks = 0; ks < 2; ++ks) {
            const int k16 = ks * 16;
            uint32_t af[4][4], bf[4][2];
            #pragma unroll
            for (int mt = 0; mt < 4; ++mt) {
                const __half* ap = &As[buf][wm + mt * 16 + g][k16 + 2 * c];
                af[mt][0] = *(const uint32_t*)ap;
                af[mt][1] = *(const uint32_t*)(ap + 8 * HST);
                af[mt][2] = *(const uint32_t*)(ap + 8);
                af[mt][3] = *(const uint32_t*)(ap + 8 * HST + 8);
            }
            #pragma unroll
            for (int nt = 0; nt < 4; ++nt) {
                const __half* bp = &Bs[buf][wn + nt * 8 + g][k16 + 2 * c];
                bf[nt][0] = *(const uint32_t*)bp;
                bf[nt][1] = *(const uint32_t*)(bp + 8);
            }
            #pragma unroll
            for (int mt = 0; mt < 4; ++mt)
                #pragma unroll
                for (int nt = 0; nt < 4; ++nt)
                    mma_h(acc[mt][nt], af[mt][0], af[mt][1], af[mt][2], af[mt][3],
                          bf[nt][0], bf[nt][1]);
        }
        __syncthreads();
    }

    #pragma unroll
    for (int mt = 0; mt < 4; ++mt) {
        #pragma unroll
        for (int nt = 0; nt < 4; ++nt) {
            int row = m0 + wm + mt * 16 + g;
            int col = n0 + wn + nt * 8 + 2 * c;
            float2 bb = *(const float2*)&bias[col];
            #pragma unroll
            for (int hh = 0; hh < 2; ++hh) {
                size_t idx = (size_t)(row + hh * 8) * N + col;
                float v0 = acc[mt][nt][hh * 2 + 0] + bb.x;
                float v1 = acc[mt][nt][hh * 2 + 1] + bb.y;
                if (EPI == 1) {
                    float2 rr = *(const float2*)&R[idx];
                    float2 o = {v0 + rr.x, v1 + rr.y};
                    *(float2*)&((float*)Cv)[idx] = o;
                } else {
                    if (EPI == 2) { v0 = gelu_exact(v0); v1 = gelu_exact(v1); }
                    __half2 o = __halves2half2(__float2half_rn(v0), __float2half_rn(v1));
                    *(__half2*)&((__half*)Cv)[idx] = o;
                }
            }
        }
    }
}

// ---------------------------------------------------------------------------
// Fused attention scores + softmax, fp16 QK^T mma.
// Block = 32 q-rows x 1024 keys for one (b,h); K streamed in 128-key chunks.
// ---------------------------------------------------------------------------
#define SMST 1032    // Sm row stride (floats)
#define QST  72      // Q/K smem row stride (halves)
#define SC_SMEM (32*SMST*4 + 32*QST*2 + 2*128*QST*2)   // 173568

__global__ void attn_scores_softmax(const __half* __restrict__ qkv, float* __restrict__ S) {
    extern __shared__ char smraw[];
    float*  Sm = (float*)smraw;                                // [32][SMST]
    __half* Qs = (__half*)(smraw + 32 * SMST * 4);             // [32][QST]
    __half* Ks = Qs + 32 * QST;                                // [2][128][QST]
    const int t = threadIdx.x;
    const int w = t >> 5, lane = t & 31, g = lane >> 2, c = lane & 3;
    const int bh = blockIdx.y, b = bh / HEADS, h = bh % HEADS;
    const int m0 = blockIdx.x * 32;
    const int wm = (w >> 2) * 16, wn = (w & 3) * 32;
    const __half* Qb = qkv + ((size_t)b * NSEQ + m0) * (3 * DIM_) + h * HDIM;
    const __half* Kb = qkv + ((size_t)b * NSEQ) * (3 * DIM_) + DIM_ + h * HDIM;

    // Q: 32 rows x 64 halves (8 chunks of 8 halves = 16B), 1 chunk/thread
    {
        int row = t >> 3, ch = t & 7;
        CP16(smem_u32(&Qs[row * QST + ch * 8]),
             Qb + (size_t)row * (3 * DIM_) + ch * 8);
        CP_COMMIT();
    }

    auto issueK = [&](int chn, int buf) {
        __half* Kd = Ks + buf * 128 * QST;
        const __half* Kg = Kb + (size_t)(chn * 128) * (3 * DIM_);
        #pragma unroll
        for (int i = 0; i < 4; ++i) {
            int li = t + i * 256;
            int key = li >> 3, ch = li & 7;
            CP16(smem_u32(&Kd[key * QST + ch * 8]),
                 Kg + (size_t)key * (3 * DIM_) + ch * 8);
        }
        CP_COMMIT();
    };
    issueK(0, 0);
    CP_WAIT0();
    __syncthreads();   // Qs + first K chunk visible

    // Q fragments: 4 k-steps over d=64
    uint32_t aq[4][4];
    #pragma unroll
    for (int ks = 0; ks < 4; ++ks) {
        const __half* ap = &Qs[(wm + g) * QST + ks * 16 + 2 * c];
        aq[ks][0] = *(const uint32_t*)ap;
        aq[ks][1] = *(const uint32_t*)(ap + 8 * QST);
        aq[ks][2] = *(const uint32_t*)(ap + 8);
        aq[ks][3] = *(const uint32_t*)(ap + 8 * QST + 8);
    }

    for (int chn = 0; chn < 8; ++chn) {
        int buf = chn & 1;
        if (chn + 1 < 8) { issueK(chn + 1, buf ^ 1); CP_WAIT1(); }
        else             { CP_WAIT0(); }
        __syncthreads();
        const __half* Kc = Ks + buf * 128 * QST;
        float acc[4][4] = {};
        #pragma unroll
        for (int ks = 0; ks < 4; ++ks) {
            #pragma unroll
            for (int nt = 0; nt < 4; ++nt) {
                const __half* bp = &Kc[(wn + nt * 8 + g) * QST + ks * 16 + 2 * c];
                uint32_t b0 = *(const uint32_t*)bp;
                uint32_t b1 = *(const uint32_t*)(bp + 8);
                mma_h(acc[nt], aq[ks][0], aq[ks][1], aq[ks][2], aq[ks][3], b0, b1);
            }
        }
        const float scl = 0.125f;
        #pragma unroll
        for (int nt = 0; nt < 4; ++nt) {
            int colb = chn * 128 + wn + nt * 8 + 2 * c;
            int row = wm + g;
            float2 o0 = {acc[nt][0] * scl, acc[nt][1] * scl};
            float2 o1 = {acc[nt][2] * scl, acc[nt][3] * scl};
            *(float2*)&Sm[row * SMST + colb]       = o0;
            *(float2*)&Sm[(row + 8) * SMST + colb] = o1;
        }
        __syncthreads();
    }

    // Softmax: warp w owns rows w*4 .. w*4+3
    #pragma unroll
    for (int i = 0; i < 4; ++i) {
        int r = w * 4 + i;
        const float* rowp = Sm + r * SMST;
        float4 v[8];
        float mx = -INFINITY;
        #pragma unroll
        for (int j = 0; j < 8; ++j) {
            v[j] = *(const float4*)(rowp + lane * 4 + j * 128);
            mx = fmaxf(mx, fmaxf(fmaxf(v[j].x, v[j].y), fmaxf(v[j].z, v[j].w)));
        }
        #pragma unroll
        for (int o = 16; o; o >>= 1) mx = fmaxf(mx, __shfl_xor_sync(0xffffffffu, mx, o));
        float s = 0.f;
        #pragma unroll
        for (int j = 0; j < 8; ++j) {
            v[j].x = __expf(v[j].x - mx); v[j].y = __expf(v[j].y - mx);
            v[j].z = __expf(v[j].z - mx); v[j].w = __expf(v[j].w - mx);
            s += v[j].x + v[j].y + v[j].z + v[j].w;
        }
        #pragma unroll
        for (int o = 16; o; o >>= 1) s += __shfl_xor_sync(0xffffffffu, s, o);
        float inv = 1.0f / s;
        float* outp = S + ((size_t)bh * NSEQ + m0 + r) * NSEQ + lane * 4;
        #pragma unroll
        for (int j = 0; j < 8; ++j) {
            float4 o = {v[j].x * inv, v[j].y * inv, v[j].z * inv, v[j].w * inv};
            *(float4*)(outp + j * 128) = o;
        }
    }
}

// ---------------------------------------------------------------------------
// PV: O = P @ V per (b,h). tf32 mma; P fp32 from attn map, V fp16 from qkv.
// 128x64 tile, K=1024 in 32-key double-buffered chunks. Writes half O.
// ---------------------------------------------------------------------------
#define VST 72   // V smem row stride in halves

__global__ void __launch_bounds__(256)
attn_pv(const float* __restrict__ S, const __half* __restrict__ qkv,
        __half* __restrict__ O) {
    __shared__ float  Ps[2][128][36];
    __shared__ __half Vs[2][32][VST];
    const int t = threadIdx.x;
    const int w = t >> 5, lane = t & 31, g = lane >> 2, c = lane & 3;
    const int bh = blockIdx.y, b = bh / HEADS, h = bh % HEADS;
    const int m0 = blockIdx.x * 128;
    const int wm = (w >> 1) * 32, wn = (w & 1) * 32;
    const float* Pb = S + ((size_t)bh * NSEQ + m0) * NSEQ;
    const __half* Vb = qkv + (size_t)b * NSEQ * (3 * DIM_) + 2 * DIM_ + h * HDIM;

    auto issue = [&](int kt, int buf) {
        #pragma unroll
        for (int i = 0; i < 4; ++i) {
            int li = t + i * 256;
            int m = li >> 3, kq = (li & 7) * 4;
            CP16(smem_u32(&Ps[buf][m][kq]), Pb + (size_t)m * NSEQ + kt * 32 + kq);
        }
        {
            int key = t >> 3, ch = t & 7;   // 32 keys x 8 chunks = 256
            CP16(smem_u32(&Vs[buf][key][ch * 8]),
                 Vb + (size_t)(kt * 32 + key) * (3 * DIM_) + ch * 8);
        }
        CP_COMMIT();
    };

    issue(0, 0);
    float acc[2][4][4] = {};
    for (int kt = 0; kt < 32; ++kt) {
        int buf = kt & 1;
        if (kt + 1 < 32) { issue(kt + 1, buf ^ 1); CP_WAIT1(); }
        else             { CP_WAIT0(); }
        __syncthreads();
        #pragma unroll
        for (int ks = 0; ks < 4; ++ks) {
            const int k8 = ks * 8;
            uint32_t af[2][4], bf[4][2];
            #pragma unroll
            for (int mt = 0; mt < 2; ++mt) {
                const float* ap = &Ps[buf][wm + mt * 16 + g][k8 + c];
                af[mt][0] = __float_as_uint(tf32r(ap[0]));
                af[mt][1] = __float_as_uint(tf32r(ap[8 * 36]));
                af[mt][2] = __float_as_uint(tf32r(ap[4]));
                af[mt][3] = __float_as_uint(tf32r(ap[8 * 36 + 4]));
            }
            #pragma unroll
            for (int nt = 0; nt < 4; ++nt) {
                int n = wn + nt * 8 + g;
                // half -> f32 is exact and fits tf32's mantissa: no extra rounding
                bf[nt][0] = __float_as_uint(__half2float(Vs[buf][k8 + c][n]));
                bf[nt][1] = __float_as_uint(__half2float(Vs[buf][k8 + c + 4][n]));
            }
            #pragma unroll
            for (int mt = 0; mt < 2; ++mt)
                #pragma unroll
                for (int nt = 0; nt < 4; ++nt)
                    mma_tf32(acc[mt][nt], af[mt][0], af[mt][1], af[mt][2], af[mt][3],
                             bf[nt][0], bf[nt][1]);
        }
        __syncthreads();
    }

    #pragma unroll
    for (int mt = 0; mt < 2; ++mt) {
        #pragma unroll
        for (int nt = 0; nt < 4; ++nt) {
            int row = m0 + wm + mt * 16 + g;
            int col = wn + nt * 8 + 2 * c;
            #pragma unroll
            for (int hh = 0; hh < 2; ++hh) {
                size_t idx = ((size_t)b * NSEQ + row + hh * 8) * DIM_ + h * HDIM + col;
                __half2 o = __halves2half2(__float2half_rn(acc[mt][nt][hh * 2 + 0]),
                                           __float2half_rn(acc[mt][nt][hh * 2 + 1]));
                *(__half2*)&O[idx] = o;
            }
        }
    }
}

// ---------------------------------------------------------------------------
// Blend: y = 0.5*(a+b), fp32
// ---------------------------------------------------------------------------
__global__ void blend_kernel(const float* __restrict__ a, const float* __restrict__ b,
                             float* __restrict__ y) {
    int i = blockIdx.x * blockDim.x + threadIdx.x;
    float4 av = ((const float4*)a)[i];
    float4 bv = ((const float4*)b)[i];
    float4 o = {0.5f * (av.x + bv.x), 0.5f * (av.y + bv.y),
                0.5f * (av.z + bv.z), 0.5f * (av.w + bv.w)};
    ((float4*)y)[i] = o;
}

// ---------------------------------------------------------------------------
// Host orchestration
// ---------------------------------------------------------------------------
extern "C" void kernel_launch(void* const* d_in, const int* in_sizes, int n_in,
                              void* d_out, int out_size) {
    (void)in_sizes; (void)n_in; (void)out_size;
    const float* x = (const float*)d_in[0];
    const float* prm[24];
    for (int i = 0; i < 24; ++i) prm[i] = (const float*)d_in[1 + i];
    // per-layer: 0 qkv_w, 1 qkv_b, 2 proj_w, 3 proj_b, 4 ln1_g, 5 ln1_b,
    //            6 ln2_g, 7 ln2_b, 8 mlp_w1, 9 mlp_b1, 10 mlp_w2, 11 mlp_b2

    float* out   = (float*)d_out;
    float* attn0 = out + OUT_ELEMS;
    float* attn1 = attn0 + ATTN_ELEMS;

    __half *p_ln, *p_qkv, *p_ao, *p_h, *p_wc;
    float *p_x1, *p_x2, *p_x3;
    cudaGetSymbolAddress((void**)&p_ln,  g_ln);
    cudaGetSymbolAddress((void**)&p_qkv, g_qkv);
    cudaGetSymbolAddress((void**)&p_ao,  g_ao);
    cudaGetSymbolAddress((void**)&p_h,   g_h);
    cudaGetSymbolAddress((void**)&p_x1,  g_x1);
    cudaGetSymbolAddress((void**)&p_x2,  g_x2);
    cudaGetSymbolAddress((void**)&p_x3,  g_x3);
    cudaGetSymbolAddress((void**)&p_wc,  g_wc);

    cudaFuncSetAttribute(attn_scores_softmax,
                         cudaFuncAttributeMaxDynamicSharedMemorySize, SC_SMEM);

    dim3 blk(256);
    dim3 tblk(32, 8);

    // transpose + fp16 weights into scratch: layout [N,K]
    const int QKV_N = DIM_ * 3 * DIM_;
    const int PRJ_N = DIM_ * DIM_;
    const int W1_N  = DIM_ * MLPH;
    __half* wq[2]; __half* wp[2]; __half* w1[2]; __half* w2[2];
    for (int L = 0; L < 2; ++L) {
        __half* base = p_wc + (size_t)L * WL_STRIDE;
        wq[L] = base;
        wp[L] = base + QKV_N;
        w1[L] = base + QKV_N + PRJ_N;
        w2[L] = base + QKV_N + PRJ_N + W1_N;
        transpose_w<<<dim3(3 * DIM_ / 32, DIM_ / 32), tblk>>>(prm[L*12 + 0],  wq[L], DIM_, 3 * DIM_);
        transpose_w<<<dim3(DIM_ / 32,     DIM_ / 32), tblk>>>(prm[L*12 + 2],  wp[L], DIM_, DIM_);
        transpose_w<<<dim3(MLPH / 32,     DIM_ / 32), tblk>>>(prm[L*12 + 8],  w1[L], DIM_, MLPH);
        transpose_w<<<dim3(DIM_ / 32,     MLPH / 32), tblk>>>(prm[L*12 + 10], w2[L], MLPH, DIM_);
    }

    auto attention = [&](int L, const float* xin, float* attnbuf, float* xout) {
        const float* const* p = prm + L * 12;
        ln_kernel<<<MROWS, blk>>>(xin, p[4], p[5], p_ln);
        gemm_h<0><<<dim3(3 * DIM_ / 128, MROWS / 128), blk>>>(
            p_ln, wq[L], p[1], nullptr, p_qkv, MROWS, 3 * DIM_, DIM_);
        attn_scores_softmax<<<dim3(32, 48), blk, SC_SMEM>>>(p_qkv, attnbuf);
        attn_pv<<<dim3(8, 48), blk>>>(attnbuf, p_qkv, p_ao);
        gemm_h<1><<<dim3(DIM_ / 128, MROWS / 128), blk>>>(
            p_ao, wp[L], p[3], xin, xout, MROWS, DIM_, DIM_);
    };
    auto mlp = [&](int L, const float* xin, float* xout) {
        const float* const* p = prm + L * 12;
        ln_kernel<<<MROWS, blk>>>(xin, p[6], p[7], p_ln);
        gemm_h<2><<<dim3(MLPH / 128, MROWS / 128), blk>>>(
            p_ln, w1[L], p[9], nullptr, p_h, MROWS, MLPH, DIM_);
        gemm_h<1><<<dim3(DIM_ / 128, MROWS / 128), blk>>>(
            p_h, w2[L], p[11], xin, xout, MROWS, DIM_, MLPH);
    };

    attention(0, x,    attn0, p_x1);
    attention(1, p_x1, attn1, p_x2);
    mlp(1, p_x2, p_x3);
    blend_kernel<<<OUT_ELEMS / 4 / 256, blk>>>(p_x1, p_x3, p_x2);
    mlp(0, p_x2, out);
}

// round 8
// speedup vs baseline: 4.8220x; 1.0550x over previous
#include <cuda_runtime.h>
#include <cuda_fp16.h>
#include <math.h>
#include <stdint.h>
#include <string.h>

// ---------------------------------------------------------------------------
// FractalBlock on B200 (compute_100 toolchain => no tcgen05).
// fp16 m16n8k16 mma.sync everywhere (PV included), ldmatrix fragment loads.
// out [4,1024,768] fp32, attn0/attn1 [4,12,1024,1024] fp32.
// ---------------------------------------------------------------------------

#define B_    4
#define NSEQ  1024
#define DIM_  768
#define HEADS 12
#define HDIM  64
#define MLPH  3072
#define MROWS (B_ * NSEQ)                       // 4096
#define OUT_ELEMS   (MROWS * DIM_)              // 3145728
#define ATTN_ELEMS  (B_ * HEADS * NSEQ * NSEQ)  // 50331648

// Scratch (device globals)
__device__ __half g_ln [MROWS * DIM_];
__device__ __half g_qkv[MROWS * 3 * DIM_];
__device__ __half g_ao [MROWS * DIM_];
__device__ __half g_h  [MROWS * MLPH];
__device__ float  g_x1 [MROWS * DIM_];
__device__ float  g_x2 [MROWS * DIM_];
__device__ float  g_x3 [MROWS * DIM_];
#define WL_STRIDE 7077888
__device__ __half g_wc [2 * WL_STRIDE];

__device__ __forceinline__ float gelu_exact(float x) {
    return 0.5f * x * (1.0f + erff(x * 0.70710678118654752f));
}
__device__ __forceinline__ uint32_t h2_u32(__half2 h) {
    uint32_t u; memcpy(&u, &h, 4); return u;
}
// fp16 mma, f32 accumulate
__device__ __forceinline__ void mma_h(float d[4], uint32_t a0, uint32_t a1,
                                      uint32_t a2, uint32_t a3,
                                      uint32_t b0, uint32_t b1) {
    asm volatile(
        "mma.sync.aligned.m16n8k16.row.col.f32.f16.f16.f32 "
        "{%0,%1,%2,%3},{%4,%5,%6,%7},{%8,%9},{%0,%1,%2,%3};"
        : "+f"(d[0]), "+f"(d[1]), "+f"(d[2]), "+f"(d[3])
        : "r"(a0), "r"(a1), "r"(a2), "r"(a3), "r"(b0), "r"(b1));
}
__device__ __forceinline__ uint32_t smem_u32(const void* p) {
    return (uint32_t)__cvta_generic_to_shared(p);
}
#define CP16(dst, src) asm volatile("cp.async.cg.shared.global [%0],[%1],16;" :: "r"(dst), "l"(src))
#define CP_COMMIT()    asm volatile("cp.async.commit_group;")
#define CP_WAIT1()     asm volatile("cp.async.wait_group 1;")
#define CP_WAIT0()     asm volatile("cp.async.wait_group 0;")

// ldmatrix: 4 8x8 fp16 tiles
#define LDSM4(r, a)                                                           \
    asm volatile("ldmatrix.sync.aligned.m8n8.x4.shared.b16 {%0,%1,%2,%3},[%4];" \
        : "=r"((r)[0]), "=r"((r)[1]), "=r"((r)[2]), "=r"((r)[3]) : "r"(a))
#define LDSM4T(r, a)                                                          \
    asm volatile("ldmatrix.sync.aligned.m8n8.x4.trans.shared.b16 {%0,%1,%2,%3},[%4];" \
        : "=r"((r)[0]), "=r"((r)[1]), "=r"((r)[2]), "=r"((r)[3]) : "r"(a))

// ---------------------------------------------------------------------------
// Weight transpose + fp16 convert: dst[N,K] = h(src[K,N])
// ---------------------------------------------------------------------------
__global__ void transpose_w(const float* __restrict__ src, __half* __restrict__ dst,
                            int K, int N) {
    __shared__ float tl[32][33];
    int n0 = blockIdx.x * 32, k0 = blockIdx.y * 32;
    int tx = threadIdx.x, ty = threadIdx.y;
    #pragma unroll
    for (int j = 0; j < 4; ++j)
        tl[ty + 8 * j][tx] = src[(size_t)(k0 + ty + 8 * j) * N + n0 + tx];
    __syncthreads();
    #pragma unroll
    for (int j = 0; j < 4; ++j)
        dst[(size_t)(n0 + ty + 8 * j) * K + k0 + tx] = __float2half_rn(tl[tx][ty + 8 * j]);
}

// ---------------------------------------------------------------------------
// LayerNorm: fp32 in -> fp16 out
// ---------------------------------------------------------------------------
__global__ void ln_kernel(const float* __restrict__ x, const float* __restrict__ g,
                          const float* __restrict__ beta, __half* __restrict__ y) {
    int row = blockIdx.x, t = threadIdx.x;
    const float* xr = x + (size_t)row * DIM_;
    float v0 = xr[t], v1 = xr[t + 256], v2 = xr[t + 512];
    float s = v0 + v1 + v2;
    float q = v0 * v0 + v1 * v1 + v2 * v2;
    __shared__ float rs[8], rq[8];
    #pragma unroll
    for (int o = 16; o; o >>= 1) {
        s += __shfl_xor_sync(0xffffffffu, s, o);
        q += __shfl_xor_sync(0xffffffffu, q, o);
    }
    int lane = t & 31, w = t >> 5;
    if (!lane) { rs[w] = s; rq[w] = q; }
    __syncthreads();
    float S = 0.f, Q = 0.f;
    #pragma unroll
    for (int i = 0; i < 8; ++i) { S += rs[i]; Q += rq[i]; }
    float mean = S * (1.0f / DIM_);
    float var  = Q * (1.0f / DIM_) - mean * mean;
    float inv  = rsqrtf(var + 1e-5f);
    __half* yr = y + (size_t)row * DIM_;
    yr[t]       = __float2half_rn((v0 - mean) * inv * g[t]       + beta[t]);
    yr[t + 256] = __float2half_rn((v1 - mean) * inv * g[t + 256] + beta[t + 256]);
    yr[t + 512] = __float2half_rn((v2 - mean) * inv * g[t + 512] + beta[t + 512]);
}

// ---------------------------------------------------------------------------
// fp16 GEMM: C[M,N] = A[M,K] @ Wt[N,K]^T + bias (+res | +gelu)
// 128x128 tile, BK=32 halves, 256 thr (8 warps 2x4), double-buffered cp.async.
// Fragments via ldmatrix.x4.
// EPI: 0 = bias -> half out; 1 = bias+residual -> fp32 out; 2 = bias+gelu -> half out
// ---------------------------------------------------------------------------
#define HST 40    // smem row stride in halves (80B)

template<int EPI>
__global__ void __launch_bounds__(256)
gemm_h(const __half* __restrict__ A, const __half* __restrict__ Wt,
       const float* __restrict__ bias, const float* __restrict__ R,
       void* __restrict__ Cv, int M, int N, int K) {
    __shared__ __half As[2][128][HST];
    __shared__ __half Bs[2][128][HST];
    const int t = threadIdx.x;
    const int w = t >> 5, lane = t & 31, g = lane >> 2, c = lane & 3;
    const int wm = (w >> 2) * 64, wn = (w & 3) * 32;
    const int m0 = blockIdx.y * 128, n0 = blockIdx.x * 128;
    const int NT = K / 32;
    const int lrow = lane & 15;
    const int lcolA = (lane >> 4) * 8;
    const int browB = (lane >> 4) * 8 + (lane & 7);
    const int bcolB = lane & 8;

    auto issue = [&](int kt, int buf) {
        #pragma unroll
        for (int i = 0; i < 2; ++i) {
            int li = t + i * 256;
            int row = li >> 2, ch = li & 3;
            CP16(smem_u32(&As[buf][row][ch * 8]),
                 A + (size_t)(m0 + row) * K + kt * 32 + ch * 8);
            CP16(smem_u32(&Bs[buf][row][ch * 8]),
                 Wt + (size_t)(n0 + row) * K + kt * 32 + ch * 8);
        }
        CP_COMMIT();
    };

    issue(0, 0);
    float acc[4][4][4] = {};
    for (int kt = 0; kt < NT; ++kt) {
        int buf = kt & 1;
        if (kt + 1 < NT) { issue(kt + 1, buf ^ 1); CP_WAIT1(); }
        else             { CP_WAIT0(); }
        __syncthreads();
        #pragma unroll
        for (int ks = 0; ks < 2; ++ks) {
            const int k16 = ks * 16;
            uint32_t af[4][4], bf[2][4];
            #pragma unroll
            for (int mt = 0; mt < 4; ++mt)
                LDSM4(af[mt], smem_u32(&As[buf][wm + mt * 16 + lrow][k16 + lcolA]));
            #pragma unroll
            for (int np = 0; np < 2; ++np)
                LDSM4(bf[np], smem_u32(&Bs[buf][wn + np * 16 + browB][k16 + bcolB]));
            #pragma unroll
            for (int mt = 0; mt < 4; ++mt)
                #pragma unroll
                for (int np = 0; np < 2; ++np) {
                    mma_h(acc[mt][np * 2 + 0], af[mt][0], af[mt][1], af[mt][2], af[mt][3],
                          bf[np][0], bf[np][1]);
                    mma_h(acc[mt][np * 2 + 1], af[mt][0], af[mt][1], af[mt][2], af[mt][3],
                          bf[np][2], bf[np][3]);
                }
        }
        __syncthreads();
    }

    #pragma unroll
    for (int mt = 0; mt < 4; ++mt) {
        #pragma unroll
        for (int nt = 0; nt < 4; ++nt) {
            int row = m0 + wm + mt * 16 + g;
            int col = n0 + wn + nt * 8 + 2 * c;
            float2 bb = *(const float2*)&bias[col];
            #pragma unroll
            for (int hh = 0; hh < 2; ++hh) {
                size_t idx = (size_t)(row + hh * 8) * N + col;
                float v0 = acc[mt][nt][hh * 2 + 0] + bb.x;
                float v1 = acc[mt][nt][hh * 2 + 1] + bb.y;
                if (EPI == 1) {
                    float2 rr = *(const float2*)&R[idx];
                    float2 o = {v0 + rr.x, v1 + rr.y};
                    *(float2*)&((float*)Cv)[idx] = o;
                } else {
                    if (EPI == 2) { v0 = gelu_exact(v0); v1 = gelu_exact(v1); }
                    __half2 o = __halves2half2(__float2half_rn(v0), __float2half_rn(v1));
                    *(__half2*)&((__half*)Cv)[idx] = o;
                }
            }
        }
    }
}

// ---------------------------------------------------------------------------
// Fused attention scores + softmax, fp16 QK^T mma with ldmatrix fragments.
// Block = 32 q-rows x 1024 keys for one (b,h); K streamed in 128-key chunks.
// ---------------------------------------------------------------------------
#define SMST 1032    // Sm row stride (floats)
#define QST  72      // Q/K smem row stride (halves)
#define SC_SMEM (32*SMST*4 + 32*QST*2 + 2*128*QST*2)   // 173568

__global__ void attn_scores_softmax(const __half* __restrict__ qkv, float* __restrict__ S) {
    extern __shared__ char smraw[];
    float*  Sm = (float*)smraw;                                // [32][SMST]
    __half* Qs = (__half*)(smraw + 32 * SMST * 4);             // [32][QST]
    __half* Ks = Qs + 32 * QST;                                // [2][128][QST]
    const int t = threadIdx.x;
    const int w = t >> 5, lane = t & 31, g = lane >> 2, c = lane & 3;
    const int bh = blockIdx.y, b = bh / HEADS, h = bh % HEADS;
    const int m0 = blockIdx.x * 32;
    const int wm = (w >> 2) * 16, wn = (w & 3) * 32;
    const __half* Qb = qkv + ((size_t)b * NSEQ + m0) * (3 * DIM_) + h * HDIM;
    const __half* Kb = qkv + ((size_t)b * NSEQ) * (3 * DIM_) + DIM_ + h * HDIM;
    const int lrow = lane & 15;
    const int lcolA = (lane >> 4) * 8;
    const int browB = (lane >> 4) * 8 + (lane & 7);
    const int bcolB = lane & 8;

    // Q: 32 rows x 64 halves
    {
        int row = t >> 3, ch = t & 7;
        CP16(smem_u32(&Qs[row * QST + ch * 8]),
             Qb + (size_t)row * (3 * DIM_) + ch * 8);
        CP_COMMIT();
    }

    auto issueK = [&](int chn, int buf) {
        __half* Kd = Ks + buf * 128 * QST;
        const __half* Kg = Kb + (size_t)(chn * 128) * (3 * DIM_);
        #pragma unroll
        for (int i = 0; i < 4; ++i) {
            int li = t + i * 256;
            int key = li >> 3, ch = li & 7;
            CP16(smem_u32(&Kd[key * QST + ch * 8]),
                 Kg + (size_t)key * (3 * DIM_) + ch * 8);
        }
        CP_COMMIT();
    };
    issueK(0, 0);
    CP_WAIT0();
    __syncthreads();   // Qs + first K chunk visible

    uint32_t aq[4][4];
    #pragma unroll
    for (int ks = 0; ks < 4; ++ks)
        LDSM4(aq[ks], smem_u32(&Qs[(wm + lrow) * QST + ks * 16 + lcolA]));

    for (int chn = 0; chn < 8; ++chn) {
        int buf = chn & 1;
        if (chn + 1 < 8) { issueK(chn + 1, buf ^ 1); CP_WAIT1(); }
        else             { CP_WAIT0(); }
        __syncthreads();
        const __half* Kc = Ks + buf * 128 * QST;
        float acc[4][4] = {};
        #pragma unroll
        for (int ks = 0; ks < 4; ++ks) {
            uint32_t bf[2][4];
            #pragma unroll
            for (int np = 0; np < 2; ++np)
                LDSM4(bf[np], smem_u32(&Kc[(wn + np * 16 + browB) * QST + ks * 16 + bcolB]));
            #pragma unroll
            for (int np = 0; np < 2; ++np) {
                mma_h(acc[np * 2 + 0], aq[ks][0], aq[ks][1], aq[ks][2], aq[ks][3],
                      bf[np][0], bf[np][1]);
                mma_h(acc[np * 2 + 1], aq[ks][0], aq[ks][1], aq[ks][2], aq[ks][3],
                      bf[np][2], bf[np][3]);
            }
        }
        const float scl = 0.125f;
        #pragma unroll
        for (int nt = 0; nt < 4; ++nt) {
            int colb = chn * 128 + wn + nt * 8 + 2 * c;
            int row = wm + g;
            float2 o0 = {acc[nt][0] * scl, acc[nt][1] * scl};
            float2 o1 = {acc[nt][2] * scl, acc[nt][3] * scl};
            *(float2*)&Sm[row * SMST + colb]       = o0;
            *(float2*)&Sm[(row + 8) * SMST + colb] = o1;
        }
        __syncthreads();
    }

    // Softmax: warp w owns rows w*4 .. w*4+3
    #pragma unroll
    for (int i = 0; i < 4; ++i) {
        int r = w * 4 + i;
        const float* rowp = Sm + r * SMST;
        float4 v[8];
        float mx = -INFINITY;
        #pragma unroll
        for (int j = 0; j < 8; ++j) {
            v[j] = *(const float4*)(rowp + lane * 4 + j * 128);
            mx = fmaxf(mx, fmaxf(fmaxf(v[j].x, v[j].y), fmaxf(v[j].z, v[j].w)));
        }
        #pragma unroll
        for (int o = 16; o; o >>= 1) mx = fmaxf(mx, __shfl_xor_sync(0xffffffffu, mx, o));
        float s = 0.f;
        #pragma unroll
        for (int j = 0; j < 8; ++j) {
            v[j].x = __expf(v[j].x - mx); v[j].y = __expf(v[j].y - mx);
            v[j].z = __expf(v[j].z - mx); v[j].w = __expf(v[j].w - mx);
            s += v[j].x + v[j].y + v[j].z + v[j].w;
        }
        #pragma unroll
        for (int o = 16; o; o >>= 1) s += __shfl_xor_sync(0xffffffffu, s, o);
        float inv = 1.0f / s;
        float* outp = S + ((size_t)bh * NSEQ + m0 + r) * NSEQ + lane * 4;
        #pragma unroll
        for (int j = 0; j < 8; ++j) {
            float4 o = {v[j].x * inv, v[j].y * inv, v[j].z * inv, v[j].w * inv};
            *(float4*)(outp + j * 128) = o;
        }
    }
}

// ---------------------------------------------------------------------------
// PV: O = P @ V per (b,h). fp16 mma; P fp32 -> half fragments, V via
// ldmatrix.x4.trans. 128x64 tile, K=1024 in 32-key chunks. Writes half O.
// ---------------------------------------------------------------------------
#define VST 72   // V smem row stride in halves

__global__ void __launch_bounds__(256)
attn_pv(const float* __restrict__ S, const __half* __restrict__ qkv,
        __half* __restrict__ O) {
    __shared__ float  Ps[2][128][36];
    __shared__ __half Vs[2][32][VST];
    const int t = threadIdx.x;
    const int w = t >> 5, lane = t & 31, g = lane >> 2, c = lane & 3;
    const int bh = blockIdx.y, b = bh / HEADS, h = bh % HEADS;
    const int m0 = blockIdx.x * 128;
    const int wm = (w >> 1) * 32, wn = (w & 1) * 32;
    const float* Pb = S + ((size_t)bh * NSEQ + m0) * NSEQ;
    const __half* Vb = qkv + (size_t)b * NSEQ * (3 * DIM_) + 2 * DIM_ + h * HDIM;
    const int lrow = lane & 15;
    const int lcol = (lane >> 4) * 8;

    auto issue = [&](int kt, int buf) {
        #pragma unroll
        for (int i = 0; i < 4; ++i) {
            int li = t + i * 256;
            int m = li >> 3, kq = (li & 7) * 4;
            CP16(smem_u32(&Ps[buf][m][kq]), Pb + (size_t)m * NSEQ + kt * 32 + kq);
        }
        {
            int key = t >> 3, ch = t & 7;
            CP16(smem_u32(&Vs[buf][key][ch * 8]),
                 Vb + (size_t)(kt * 32 + key) * (3 * DIM_) + ch * 8);
        }
        CP_COMMIT();
    };

    issue(0, 0);
    float acc[2][4][4] = {};
    for (int kt = 0; kt < 32; ++kt) {
        int buf = kt & 1;
        if (kt + 1 < 32) { issue(kt + 1, buf ^ 1); CP_WAIT1(); }
        else             { CP_WAIT0(); }
        __syncthreads();
        #pragma unroll
        for (int ks = 0; ks < 2; ++ks) {
            const int k16 = ks * 16;
            uint32_t bf[2][4];
            #pragma unroll
            for (int dp = 0; dp < 2; ++dp)
                LDSM4T(bf[dp], smem_u32(&Vs[buf][k16 + lrow][wn + dp * 16 + lcol]));
            #pragma unroll
            for (int mt = 0; mt < 2; ++mt) {
                const float* ap = &Ps[buf][wm + mt * 16 + g][k16 + 2 * c];
                float2 p0 = *(const float2*)(ap);
                float2 p1 = *(const float2*)(ap + 8 * 36);
                float2 p2 = *(const float2*)(ap + 8);
                float2 p3 = *(const float2*)(ap + 8 * 36 + 8);
                uint32_t a0 = h2_u32(__float22half2_rn(p0));
                uint32_t a1 = h2_u32(__float22half2_rn(p1));
                uint32_t a2 = h2_u32(__float22half2_rn(p2));
                uint32_t a3 = h2_u32(__float22half2_rn(p3));
                #pragma unroll
                for (int dp = 0; dp < 2; ++dp) {
                    mma_h(acc[mt][dp * 2 + 0], a0, a1, a2, a3, bf[dp][0], bf[dp][1]);
                    mma_h(acc[mt][dp * 2 + 1], a0, a1, a2, a3, bf[dp][2], bf[dp][3]);
                }
            }
        }
        __syncthreads();
    }

    #pragma unroll
    for (int mt = 0; mt < 2; ++mt) {
        #pragma unroll
        for (int nt = 0; nt < 4; ++nt) {
            int row = m0 + wm + mt * 16 + g;
            int col = wn + nt * 8 + 2 * c;
            #pragma unroll
            for (int hh = 0; hh < 2; ++hh) {
                size_t idx = ((size_t)b * NSEQ + row + hh * 8) * DIM_ + h * HDIM + col;
                __half2 o = __halves2half2(__float2half_rn(acc[mt][nt][hh * 2 + 0]),
                                           __float2half_rn(acc[mt][nt][hh * 2 + 1]));
                *(__half2*)&O[idx] = o;
            }
        }
    }
}

// ---------------------------------------------------------------------------
// Blend: y = 0.5*(a+b), fp32
// ---------------------------------------------------------------------------
__global__ void blend_kernel(const float* __restrict__ a, const float* __restrict__ b,
                             float* __restrict__ y) {
    int i = blockIdx.x * blockDim.x + threadIdx.x;
    float4 av = ((const float4*)a)[i];
    float4 bv = ((const float4*)b)[i];
    float4 o = {0.5f * (av.x + bv.x), 0.5f * (av.y + bv.y),
                0.5f * (av.z + bv.z), 0.5f * (av.w + bv.w)};
    ((float4*)y)[i] = o;
}

// ---------------------------------------------------------------------------
// Host orchestration. Launch order arranged so ncu (-s 5 -c 1) captures
// launch #6 = gemm_h<0> (qkv GEMM).
// ---------------------------------------------------------------------------
extern "C" void kernel_launch(void* const* d_in, const int* in_sizes, int n_in,
                              void* d_out, int out_size) {
    (void)in_sizes; (void)n_in; (void)out_size;
    const float* x = (const float*)d_in[0];
    const float* prm[24];
    for (int i = 0; i < 24; ++i) prm[i] = (const float*)d_in[1 + i];
    // per-layer: 0 qkv_w, 1 qkv_b, 2 proj_w, 3 proj_b, 4 ln1_g, 5 ln1_b,
    //            6 ln2_g, 7 ln2_b, 8 mlp_w1, 9 mlp_b1, 10 mlp_w2, 11 mlp_b2

    float* out   = (float*)d_out;
    float* attn0 = out + OUT_ELEMS;
    float* attn1 = attn0 + ATTN_ELEMS;

    __half *p_ln, *p_qkv, *p_ao, *p_h, *p_wc;
    float *p_x1, *p_x2, *p_x3;
    cudaGetSymbolAddress((void**)&p_ln,  g_ln);
    cudaGetSymbolAddress((void**)&p_qkv, g_qkv);
    cudaGetSymbolAddress((void**)&p_ao,  g_ao);
    cudaGetSymbolAddress((void**)&p_h,   g_h);
    cudaGetSymbolAddress((void**)&p_x1,  g_x1);
    cudaGetSymbolAddress((void**)&p_x2,  g_x2);
    cudaGetSymbolAddress((void**)&p_x3,  g_x3);
    cudaGetSymbolAddress((void**)&p_wc,  g_wc);

    cudaFuncSetAttribute(attn_scores_softmax,
                         cudaFuncAttributeMaxDynamicSharedMemorySize, SC_SMEM);

    dim3 blk(256);
    dim3 tblk(32, 8);

    const int QKV_N = DIM_ * 3 * DIM_;
    const int PRJ_N = DIM_ * DIM_;
    const int W1_N  = DIM_ * MLPH;
    __half* wq[2]; __half* wp[2]; __half* w1[2]; __half* w2[2];
    for (int L = 0; L < 2; ++L) {
        __half* base = p_wc + (size_t)L * WL_STRIDE;
        wq[L] = base;
        wp[L] = base + QKV_N;
        w1[L] = base + QKV_N + PRJ_N;
        w2[L] = base + QKV_N + PRJ_N + W1_N;
    }
    auto transposes = [&](int L) {
        transpose_w<<<dim3(3 * DIM_ / 32, DIM_ / 32), tblk>>>(prm[L*12 + 0],  wq[L], DIM_, 3 * DIM_);
        transpose_w<<<dim3(DIM_ / 32,     DIM_ / 32), tblk>>>(prm[L*12 + 2],  wp[L], DIM_, DIM_);
        transpose_w<<<dim3(MLPH / 32,     DIM_ / 32), tblk>>>(prm[L*12 + 8],  w1[L], DIM_, MLPH);
        transpose_w<<<dim3(DIM_ / 32,     MLPH / 32), tblk>>>(prm[L*12 + 10], w2[L], MLPH, DIM_);
    };

    auto attention = [&](int L, const float* xin, float* attnbuf, float* xout) {
        const float* const* p = prm + L * 12;
        ln_kernel<<<MROWS, blk>>>(xin, p[4], p[5], p_ln);
        gemm_h<0><<<dim3(3 * DIM_ / 128, MROWS / 128), blk>>>(
            p_ln, wq[L], p[1], nullptr, p_qkv, MROWS, 3 * DIM_, DIM_);
        attn_scores_softmax<<<dim3(32, 48), blk, SC_SMEM>>>(p_qkv, attnbuf);
        attn_pv<<<dim3(8, 48), blk>>>(attnbuf, p_qkv, p_ao);
        gemm_h<1><<<dim3(DIM_ / 128, MROWS / 128), blk>>>(
            p_ao, wp[L], p[3], xin, xout, MROWS, DIM_, DIM_);
    };
    auto mlp = [&](int L, const float* xin, float* xout) {
        const float* const* p = prm + L * 12;
        ln_kernel<<<MROWS, blk>>>(xin, p[6], p[7], p_ln);
        gemm_h<2><<<dim3(MLPH / 128, MROWS / 128), blk>>>(
            p_ln, w1[L], p[9], nullptr, p_h, MROWS, MLPH, DIM_);
        gemm_h<1><<<dim3(DIM_ / 128, MROWS / 128), blk>>>(
            p_h, w2[L], p[11], xin, xout, MROWS, DIM_, MLPH);
    };

    // Launches 1-4: L0 transposes; 5: ln; 6: qkv gemm (ncu captures this)
    transposes(0);
    attention(0, x,    attn0, p_x1);
    transposes(1);
    attention(1, p_x1, attn1, p_x2);
    mlp(1, p_x2, p_x3);
    blend_kernel<<<OUT_ELEMS / 4 / 256, blk>>>(p_x1, p_x3, p_x2);
    mlp(0, p_x2, out);
}

// round 9
// speedup vs baseline: 4.8245x; 1.0005x over previous
#include <cuda_runtime.h>
#include <cuda_fp16.h>
#include <math.h>
#include <stdint.h>
#include <string.h>

// ---------------------------------------------------------------------------
// FractalBlock on B200 (compute_100 toolchain => no tcgen05).
// fp16 m16n8k16 mma.sync everywhere; attention scores+softmax+PV fused.
// out [4,1024,768] fp32, attn0/attn1 [4,12,1024,1024] fp32.
// ---------------------------------------------------------------------------

#define B_    4
#define NSEQ  1024
#define DIM_  768
#define HEADS 12
#define HDIM  64
#define MLPH  3072
#define MROWS (B_ * NSEQ)                       // 4096
#define OUT_ELEMS   (MROWS * DIM_)              // 3145728
#define ATTN_ELEMS  (B_ * HEADS * NSEQ * NSEQ)  // 50331648

// Scratch (device globals)
__device__ __half g_ln [MROWS * DIM_];
__device__ __half g_qkv[MROWS * 3 * DIM_];
__device__ __half g_ao [MROWS * DIM_];
__device__ __half g_h  [MROWS * MLPH];
__device__ float  g_x1 [MROWS * DIM_];
__device__ float  g_x2 [MROWS * DIM_];
__device__ float  g_x3 [MROWS * DIM_];
#define WL_STRIDE 7077888
__device__ __half g_wc [2 * WL_STRIDE];

__device__ __forceinline__ float gelu_exact(float x) {
    return 0.5f * x * (1.0f + erff(x * 0.70710678118654752f));
}
__device__ __forceinline__ uint32_t h2_u32(__half2 h) {
    uint32_t u; memcpy(&u, &h, 4); return u;
}
// fp16 mma, f32 accumulate
__device__ __forceinline__ void mma_h(float d[4], uint32_t a0, uint32_t a1,
                                      uint32_t a2, uint32_t a3,
                                      uint32_t b0, uint32_t b1) {
    asm volatile(
        "mma.sync.aligned.m16n8k16.row.col.f32.f16.f16.f32 "
        "{%0,%1,%2,%3},{%4,%5,%6,%7},{%8,%9},{%0,%1,%2,%3};"
        : "+f"(d[0]), "+f"(d[1]), "+f"(d[2]), "+f"(d[3])
        : "r"(a0), "r"(a1), "r"(a2), "r"(a3), "r"(b0), "r"(b1));
}
__device__ __forceinline__ uint32_t smem_u32(const void* p) {
    return (uint32_t)__cvta_generic_to_shared(p);
}
#define CP16(dst, src) asm volatile("cp.async.cg.shared.global [%0],[%1],16;" :: "r"(dst), "l"(src))
#define CP_COMMIT()    asm volatile("cp.async.commit_group;")
#define CP_WAIT1()     asm volatile("cp.async.wait_group 1;")
#define CP_WAIT0()     asm volatile("cp.async.wait_group 0;")

// ldmatrix: 4 8x8 fp16 tiles
#define LDSM4(r, a)                                                           \
    asm volatile("ldmatrix.sync.aligned.m8n8.x4.shared.b16 {%0,%1,%2,%3},[%4];" \
        : "=r"((r)[0]), "=r"((r)[1]), "=r"((r)[2]), "=r"((r)[3]) : "r"(a))
#define LDSM4T(r, a)                                                          \
    asm volatile("ldmatrix.sync.aligned.m8n8.x4.trans.shared.b16 {%0,%1,%2,%3},[%4];" \
        : "=r"((r)[0]), "=r"((r)[1]), "=r"((r)[2]), "=r"((r)[3]) : "r"(a))

// ---------------------------------------------------------------------------
// Weight transpose + fp16 convert: dst[N,K] = h(src[K,N])
// ---------------------------------------------------------------------------
__global__ void transpose_w(const float* __restrict__ src, __half* __restrict__ dst,
                            int K, int N) {
    __shared__ float tl[32][33];
    int n0 = blockIdx.x * 32, k0 = blockIdx.y * 32;
    int tx = threadIdx.x, ty = threadIdx.y;
    #pragma unroll
    for (int j = 0; j < 4; ++j)
        tl[ty + 8 * j][tx] = src[(size_t)(k0 + ty + 8 * j) * N + n0 + tx];
    __syncthreads();
    #pragma unroll
    for (int j = 0; j < 4; ++j)
        dst[(size_t)(n0 + ty + 8 * j) * K + k0 + tx] = __float2half_rn(tl[tx][ty + 8 * j]);
}

// ---------------------------------------------------------------------------
// LayerNorm: fp32 in -> fp16 out
// ---------------------------------------------------------------------------
__global__ void ln_kernel(const float* __restrict__ x, const float* __restrict__ g,
                          const float* __restrict__ beta, __half* __restrict__ y) {
    int row = blockIdx.x, t = threadIdx.x;
    const float* xr = x + (size_t)row * DIM_;
    float v0 = xr[t], v1 = xr[t + 256], v2 = xr[t + 512];
    float s = v0 + v1 + v2;
    float q = v0 * v0 + v1 * v1 + v2 * v2;
    __shared__ float rs[8], rq[8];
    #pragma unroll
    for (int o = 16; o; o >>= 1) {
        s += __shfl_xor_sync(0xffffffffu, s, o);
        q += __shfl_xor_sync(0xffffffffu, q, o);
    }
    int lane = t & 31, w = t >> 5;
    if (!lane) { rs[w] = s; rq[w] = q; }
    __syncthreads();
    float S = 0.f, Q = 0.f;
    #pragma unroll
    for (int i = 0; i < 8; ++i) { S += rs[i]; Q += rq[i]; }
    float mean = S * (1.0f / DIM_);
    float var  = Q * (1.0f / DIM_) - mean * mean;
    float inv  = rsqrtf(var + 1e-5f);
    __half* yr = y + (size_t)row * DIM_;
    yr[t]       = __float2half_rn((v0 - mean) * inv * g[t]       + beta[t]);
    yr[t + 256] = __float2half_rn((v1 - mean) * inv * g[t + 256] + beta[t + 256]);
    yr[t + 512] = __float2half_rn((v2 - mean) * inv * g[t + 512] + beta[t + 512]);
}

// ---------------------------------------------------------------------------
// fp16 GEMM: C[M,N] = A[M,K] @ Wt[N,K]^T + bias (+res | +gelu)
// 128x128 tile, BK=32 halves, 256 thr (8 warps 2x4), double-buffered cp.async.
// Fragments via ldmatrix.x4.
// EPI: 0 = bias -> half out; 1 = bias+residual -> fp32 out; 2 = bias+gelu -> half out
// ---------------------------------------------------------------------------
#define HST 40    // smem row stride in halves (80B)

template<int EPI>
__global__ void __launch_bounds__(256)
gemm_h(const __half* __restrict__ A, const __half* __restrict__ Wt,
       const float* __restrict__ bias, const float* __restrict__ R,
       void* __restrict__ Cv, int M, int N, int K) {
    __shared__ __half As[2][128][HST];
    __shared__ __half Bs[2][128][HST];
    const int t = threadIdx.x;
    const int w = t >> 5, lane = t & 31, g = lane >> 2, c = lane & 3;
    const int wm = (w >> 2) * 64, wn = (w & 3) * 32;
    const int m0 = blockIdx.y * 128, n0 = blockIdx.x * 128;
    const int NT = K / 32;
    const int lrow = lane & 15;
    const int lcolA = (lane >> 4) * 8;
    const int browB = (lane >> 4) * 8 + (lane & 7);
    const int bcolB = lane & 8;

    auto issue = [&](int kt, int buf) {
        #pragma unroll
        for (int i = 0; i < 2; ++i) {
            int li = t + i * 256;
            int row = li >> 2, ch = li & 3;
            CP16(smem_u32(&As[buf][row][ch * 8]),
                 A + (size_t)(m0 + row) * K + kt * 32 + ch * 8);
            CP16(smem_u32(&Bs[buf][row][ch * 8]),
                 Wt + (size_t)(n0 + row) * K + kt * 32 + ch * 8);
        }
        CP_COMMIT();
    };

    issue(0, 0);
    float acc[4][4][4] = {};
    for (int kt = 0; kt < NT; ++kt) {
        int buf = kt & 1;
        if (kt + 1 < NT) { issue(kt + 1, buf ^ 1); CP_WAIT1(); }
        else             { CP_WAIT0(); }
        __syncthreads();
        #pragma unroll
        for (int ks = 0; ks < 2; ++ks) {
            const int k16 = ks * 16;
            uint32_t af[4][4], bf[2][4];
            #pragma unroll
            for (int mt = 0; mt < 4; ++mt)
                LDSM4(af[mt], smem_u32(&As[buf][wm + mt * 16 + lrow][k16 + lcolA]));
            #pragma unroll
            for (int np = 0; np < 2; ++np)
                LDSM4(bf[np], smem_u32(&Bs[buf][wn + np * 16 + browB][k16 + bcolB]));
            #pragma unroll
            for (int mt = 0; mt < 4; ++mt)
                #pragma unroll
                for (int np = 0; np < 2; ++np) {
                    mma_h(acc[mt][np * 2 + 0], af[mt][0], af[mt][1], af[mt][2], af[mt][3],
                          bf[np][0], bf[np][1]);
                    mma_h(acc[mt][np * 2 + 1], af[mt][0], af[mt][1], af[mt][2], af[mt][3],
                          bf[np][2], bf[np][3]);
                }
        }
        __syncthreads();
    }

    #pragma unroll
    for (int mt = 0; mt < 4; ++mt) {
        #pragma unroll
        for (int nt = 0; nt < 4; ++nt) {
            int row = m0 + wm + mt * 16 + g;
            int col = n0 + wn + nt * 8 + 2 * c;
            float2 bb = *(const float2*)&bias[col];
            #pragma unroll
            for (int hh = 0; hh < 2; ++hh) {
                size_t idx = (size_t)(row + hh * 8) * N + col;
                float v0 = acc[mt][nt][hh * 2 + 0] + bb.x;
                float v1 = acc[mt][nt][hh * 2 + 1] + bb.y;
                if (EPI == 1) {
                    float2 rr = *(const float2*)&R[idx];
                    float2 o = {v0 + rr.x, v1 + rr.y};
                    *(float2*)&((float*)Cv)[idx] = o;
                } else {
                    if (EPI == 2) { v0 = gelu_exact(v0); v1 = gelu_exact(v1); }
                    __half2 o = __halves2half2(__float2half_rn(v0), __float2half_rn(v1));
                    *(__half2*)&((__half*)Cv)[idx] = o;
                }
            }
        }
    }
}

// ---------------------------------------------------------------------------
// Fused attention: scores (fp16 mma) + softmax + attn-map write + PV (fp16 mma).
// Block = 32 q-rows x 1024 keys for one (b,h).
// Smem: Sm fp32 scores [32][1036] (P half written in-place), Q tile, K/V ring.
// ---------------------------------------------------------------------------
#define SMST 1036    // Sm row stride (floats); 4144B = 48 mod 128 -> ldmatrix-safe
#define SMSTH (2 * SMST)   // same rows viewed as halves
#define QST  72      // Q/K/V smem row stride (halves)
#define SC_SMEM (32*SMST*4 + 32*QST*2 + 2*128*QST*2)   // 174080

__global__ void attn_fused(const __half* __restrict__ qkv, float* __restrict__ S,
                           __half* __restrict__ O) {
    extern __shared__ char smraw[];
    float*  Sm = (float*)smraw;                                // [32][SMST]
    __half* SmH = (__half*)smraw;                              // P half view
    __half* Qs = (__half*)(smraw + 32 * SMST * 4);             // [32][QST]
    __half* KV = Qs + 32 * QST;                                // [2][128][QST]
    const int t = threadIdx.x;
    const int w = t >> 5, lane = t & 31, g = lane >> 2, c = lane & 3;
    const int bh = blockIdx.y, b = bh / HEADS, h = bh % HEADS;
    const int m0 = blockIdx.x * 32;
    const int wm = (w >> 2) * 16, wn = (w & 3) * 32;
    const __half* Qb = qkv + ((size_t)b * NSEQ + m0) * (3 * DIM_) + h * HDIM;
    const __half* Kb = qkv + ((size_t)b * NSEQ) * (3 * DIM_) + DIM_ + h * HDIM;
    const __half* Vb = qkv + ((size_t)b * NSEQ) * (3 * DIM_) + 2 * DIM_ + h * HDIM;
    const int lrow = lane & 15;
    const int lcolA = (lane >> 4) * 8;
    const int browB = (lane >> 4) * 8 + (lane & 7);
    const int bcolB = lane & 8;

    // Q: 32 rows x 64 halves
    {
        int row = t >> 3, ch = t & 7;
        CP16(smem_u32(&Qs[row * QST + ch * 8]),
             Qb + (size_t)row * (3 * DIM_) + ch * 8);
        CP_COMMIT();
    }

    auto issueKV = [&](const __half* base, int chn, int buf) {
        __half* Kd = KV + buf * 128 * QST;
        const __half* Kg = base + (size_t)(chn * 128) * (3 * DIM_);
        #pragma unroll
        for (int i = 0; i < 4; ++i) {
            int li = t + i * 256;
            int key = li >> 3, ch = li & 7;
            CP16(smem_u32(&Kd[key * QST + ch * 8]),
                 Kg + (size_t)key * (3 * DIM_) + ch * 8);
        }
        CP_COMMIT();
    };
    issueKV(Kb, 0, 0);
    CP_WAIT0();
    __syncthreads();   // Qs + first K chunk visible

    // Q fragments: 4 k-steps over d=64
    uint32_t aq[4][4];
    #pragma unroll
    for (int ks = 0; ks < 4; ++ks)
        LDSM4(aq[ks], smem_u32(&Qs[(wm + lrow) * QST + ks * 16 + lcolA]));

    // ---- Phase 1: scores ----
    for (int chn = 0; chn < 8; ++chn) {
        int buf = chn & 1;
        if (chn + 1 < 8) { issueKV(Kb, chn + 1, buf ^ 1); CP_WAIT1(); }
        else             { CP_WAIT0(); }
        __syncthreads();
        const __half* Kc = KV + buf * 128 * QST;
        float acc[4][4] = {};
        #pragma unroll
        for (int ks = 0; ks < 4; ++ks) {
            uint32_t bf[2][4];
            #pragma unroll
            for (int np = 0; np < 2; ++np)
                LDSM4(bf[np], smem_u32(&Kc[(wn + np * 16 + browB) * QST + ks * 16 + bcolB]));
            #pragma unroll
            for (int np = 0; np < 2; ++np) {
                mma_h(acc[np * 2 + 0], aq[ks][0], aq[ks][1], aq[ks][2], aq[ks][3],
                      bf[np][0], bf[np][1]);
                mma_h(acc[np * 2 + 1], aq[ks][0], aq[ks][1], aq[ks][2], aq[ks][3],
                      bf[np][2], bf[np][3]);
            }
        }
        const float scl = 0.125f;
        #pragma unroll
        for (int nt = 0; nt < 4; ++nt) {
            int colb = chn * 128 + wn + nt * 8 + 2 * c;
            int row = wm + g;
            float2 o0 = {acc[nt][0] * scl, acc[nt][1] * scl};
            float2 o1 = {acc[nt][2] * scl, acc[nt][3] * scl};
            *(float2*)&Sm[row * SMST + colb]       = o0;
            *(float2*)&Sm[(row + 8) * SMST + colb] = o1;
        }
        __syncthreads();
    }

    // Prefetch V chunks 0,1 (overlaps with softmax below)
    issueKV(Vb, 0, 0);
    issueKV(Vb, 1, 1);

    // ---- Phase 2: softmax; write fp32 attn map + half P in place ----
    #pragma unroll
    for (int i = 0; i < 4; ++i) {
        int r = w * 4 + i;
        const float* rowp = Sm + r * SMST;
        __half* hrow = SmH + r * SMSTH;
        float4 v[8];
        float mx = -INFINITY;
        #pragma unroll
        for (int j = 0; j < 8; ++j) {
            v[j] = *(const float4*)(rowp + lane * 4 + j * 128);
            mx = fmaxf(mx, fmaxf(fmaxf(v[j].x, v[j].y), fmaxf(v[j].z, v[j].w)));
        }
        #pragma unroll
        for (int o = 16; o; o >>= 1) mx = fmaxf(mx, __shfl_xor_sync(0xffffffffu, mx, o));
        float s = 0.f;
        #pragma unroll
        for (int j = 0; j < 8; ++j) {
            v[j].x = __expf(v[j].x - mx); v[j].y = __expf(v[j].y - mx);
            v[j].z = __expf(v[j].z - mx); v[j].w = __expf(v[j].w - mx);
            s += v[j].x + v[j].y + v[j].z + v[j].w;
        }
        #pragma unroll
        for (int o = 16; o; o >>= 1) s += __shfl_xor_sync(0xffffffffu, s, o);
        float inv = 1.0f / s;
        float* outp = S + ((size_t)bh * NSEQ + m0 + r) * NSEQ + lane * 4;
        #pragma unroll
        for (int j = 0; j < 8; ++j) {
            float4 o = {v[j].x * inv, v[j].y * inv, v[j].z * inv, v[j].w * inv};
            *(float4*)(outp + j * 128) = o;
            // half P in place (warp owns the row; all loads above precede stores)
            __half2 h0 = __floats2half2_rn(o.x, o.y);
            __half2 h1 = __floats2half2_rn(o.z, o.w);
            uint2 hp = {h2_u32(h0), h2_u32(h1)};
            *(uint2*)(hrow + lane * 4 + j * 128) = hp;
        }
    }

    // ---- Phase 3: PV ----
    // Warp tile: 16 rows x 16 d-cols; wm2 row group, wn2 col group.
    const int wm2 = (w >> 2) * 16, wn2 = (w & 3) * 16;
    float acc2[2][4] = {};
    for (int chn = 0; chn < 8; ++chn) {
        int buf = chn & 1;
        if (chn + 2 < 8) CP_WAIT1(); else CP_WAIT0();
        __syncthreads();   // V chunk ready; also orders softmax P writes
        const __half* Vc = KV + buf * 128 * QST;
        #pragma unroll
        for (int ks = 0; ks < 8; ++ks) {
            const int k16 = ks * 16;
            uint32_t pf[4], vf[4];
            LDSM4(pf, smem_u32(&SmH[(wm2 + lrow) * SMSTH + chn * 128 + k16 + lcolA]));
            LDSM4T(vf, smem_u32(&Vc[(k16 + lrow) * QST + wn2 + lcolA]));
            mma_h(acc2[0], pf[0], pf[1], pf[2], pf[3], vf[0], vf[1]);
            mma_h(acc2[1], pf[0], pf[1], pf[2], pf[3], vf[2], vf[3]);
        }
        __syncthreads();
        if (chn + 2 < 8) issueKV(Vb, chn + 2, buf);
    }

    // O epilogue: rows m0+wm2+g(+8), cols wn2 + nt*8 + 2c -> g_ao half
    #pragma unroll
    for (int nt = 0; nt < 2; ++nt) {
        int col = wn2 + nt * 8 + 2 * c;
        #pragma unroll
        for (int hh = 0; hh < 2; ++hh) {
            int row = m0 + wm2 + g + hh * 8;
            size_t idx = ((size_t)b * NSEQ + row) * DIM_ + h * HDIM + col;
            __half2 o = __halves2half2(__float2half_rn(acc2[nt][hh * 2 + 0]),
                                       __float2half_rn(acc2[nt][hh * 2 + 1]));
            *(__half2*)&O[idx] = o;
        }
    }
}

// ---------------------------------------------------------------------------
// Blend: y = 0.5*(a+b), fp32
// ---------------------------------------------------------------------------
__global__ void blend_kernel(const float* __restrict__ a, const float* __restrict__ b,
                             float* __restrict__ y) {
    int i = blockIdx.x * blockDim.x + threadIdx.x;
    float4 av = ((const float4*)a)[i];
    float4 bv = ((const float4*)b)[i];
    float4 o = {0.5f * (av.x + bv.x), 0.5f * (av.y + bv.y),
                0.5f * (av.z + bv.z), 0.5f * (av.w + bv.w)};
    ((float4*)y)[i] = o;
}

// ---------------------------------------------------------------------------
// Host orchestration
// ---------------------------------------------------------------------------
extern "C" void kernel_launch(void* const* d_in, const int* in_sizes, int n_in,
                              void* d_out, int out_size) {
    (void)in_sizes; (void)n_in; (void)out_size;
    const float* x = (const float*)d_in[0];
    const float* prm[24];
    for (int i = 0; i < 24; ++i) prm[i] = (const float*)d_in[1 + i];
    // per-layer: 0 qkv_w, 1 qkv_b, 2 proj_w, 3 proj_b, 4 ln1_g, 5 ln1_b,
    //            6 ln2_g, 7 ln2_b, 8 mlp_w1, 9 mlp_b1, 10 mlp_w2, 11 mlp_b2

    float* out   = (float*)d_out;
    float* attn0 = out + OUT_ELEMS;
    float* attn1 = attn0 + ATTN_ELEMS;

    __half *p_ln, *p_qkv, *p_ao, *p_h, *p_wc;
    float *p_x1, *p_x2, *p_x3;
    cudaGetSymbolAddress((void**)&p_ln,  g_ln);
    cudaGetSymbolAddress((void**)&p_qkv, g_qkv);
    cudaGetSymbolAddress((void**)&p_ao,  g_ao);
    cudaGetSymbolAddress((void**)&p_h,   g_h);
    cudaGetSymbolAddress((void**)&p_x1,  g_x1);
    cudaGetSymbolAddress((void**)&p_x2,  g_x2);
    cudaGetSymbolAddress((void**)&p_x3,  g_x3);
    cudaGetSymbolAddress((void**)&p_wc,  g_wc);

    cudaFuncSetAttribute(attn_fused,
                         cudaFuncAttributeMaxDynamicSharedMemorySize, SC_SMEM);

    dim3 blk(256);
    dim3 tblk(32, 8);

    const int QKV_N = DIM_ * 3 * DIM_;
    const int PRJ_N = DIM_ * DIM_;
    const int W1_N  = DIM_ * MLPH;
    __half* wq[2]; __half* wp[2]; __half* w1[2]; __half* w2[2];
    for (int L = 0; L < 2; ++L) {
        __half* base = p_wc + (size_t)L * WL_STRIDE;
        wq[L] = base;
        wp[L] = base + QKV_N;
        w1[L] = base + QKV_N + PRJ_N;
        w2[L] = base + QKV_N + PRJ_N + W1_N;
    }
    auto transposes = [&](int L) {
        transpose_w<<<dim3(3 * DIM_ / 32, DIM_ / 32), tblk>>>(prm[L*12 + 0],  wq[L], DIM_, 3 * DIM_);
        transpose_w<<<dim3(DIM_ / 32,     DIM_ / 32), tblk>>>(prm[L*12 + 2],  wp[L], DIM_, DIM_);
        transpose_w<<<dim3(MLPH / 32,     DIM_ / 32), tblk>>>(prm[L*12 + 8],  w1[L], DIM_, MLPH);
        transpose_w<<<dim3(DIM_ / 32,     MLPH / 32), tblk>>>(prm[L*12 + 10], w2[L], MLPH, DIM_);
    };

    auto attention = [&](int L, const float* xin, float* attnbuf, float* xout) {
        const float* const* p = prm + L * 12;
        ln_kernel<<<MROWS, blk>>>(xin, p[4], p[5], p_ln);
        gemm_h<0><<<dim3(3 * DIM_ / 128, MROWS / 128), blk>>>(
            p_ln, wq[L], p[1], nullptr, p_qkv, MROWS, 3 * DIM_, DIM_);
        attn_fused<<<dim3(32, 48), blk, SC_SMEM>>>(p_qkv, attnbuf, p_ao);
        gemm_h<1><<<dim3(DIM_ / 128, MROWS / 128), blk>>>(
            p_ao, wp[L], p[3], xin, xout, MROWS, DIM_, DIM_);
    };
    auto mlp = [&](int L, const float* xin, float* xout) {
        const float* const* p = prm + L * 12;
        ln_kernel<<<MROWS, blk>>>(xin, p[6], p[7], p_ln);
        gemm_h<2><<<dim3(MLPH / 128, MROWS / 128), blk>>>(
            p_ln, w1[L], p[9], nullptr, p_h, MROWS, MLPH, DIM_);
        gemm_h<1><<<dim3(DIM_ / 128, MROWS / 128), blk>>>(
            p_h, w2[L], p[11], xin, xout, MROWS, DIM_, MLPH);
    };

    transposes(0);
    attention(0, x,    attn0, p_x1);
    transposes(1);
    attention(1, p_x1, attn1, p_x2);
    mlp(1, p_x2, p_x3);
    blend_kernel<<<OUT_ELEMS / 4 / 256, blk>>>(p_x1, p_x3, p_x2);
    mlp(0, p_x2, out);
}

// round 10
// speedup vs baseline: 5.0919x; 1.0554x over previous
#include <cuda_runtime.h>
#include <cuda_fp16.h>
#include <math.h>
#include <stdint.h>
#include <string.h>

// ---------------------------------------------------------------------------
// FractalBlock on B200 (compute_100 toolchain => no tcgen05).
// fp16 m16n8k16 mma.sync; B operands via ldmatrix.trans from native [K,N]
// weights (no transpose pass). Fused attention scores+softmax+PV.
// out [4,1024,768] fp32, attn0/attn1 [4,12,1024,1024] fp32.
// ---------------------------------------------------------------------------

#define B_    4
#define NSEQ  1024
#define DIM_  768
#define HEADS 12
#define HDIM  64
#define MLPH  3072
#define MROWS (B_ * NSEQ)                       // 4096
#define OUT_ELEMS   (MROWS * DIM_)              // 3145728
#define ATTN_ELEMS  (B_ * HEADS * NSEQ * NSEQ)  // 50331648

// Scratch (device globals)
__device__ __half g_ln [MROWS * DIM_];
__device__ __half g_qkv[MROWS * 3 * DIM_];
__device__ __half g_ao [MROWS * DIM_];
__device__ __half g_h  [MROWS * MLPH];
__device__ float  g_x1 [MROWS * DIM_];
__device__ float  g_x2 [MROWS * DIM_];
__device__ float  g_x3 [MROWS * DIM_];
#define WL_STRIDE 7077888
__device__ __half g_wc [2 * WL_STRIDE];

__device__ __forceinline__ float gelu_exact(float x) {
    return 0.5f * x * (1.0f + erff(x * 0.70710678118654752f));
}
__device__ __forceinline__ uint32_t h2_u32(__half2 h) {
    uint32_t u; memcpy(&u, &h, 4); return u;
}
// fp16 mma, f32 accumulate
__device__ __forceinline__ void mma_h(float d[4], uint32_t a0, uint32_t a1,
                                      uint32_t a2, uint32_t a3,
                                      uint32_t b0, uint32_t b1) {
    asm volatile(
        "mma.sync.aligned.m16n8k16.row.col.f32.f16.f16.f32 "
        "{%0,%1,%2,%3},{%4,%5,%6,%7},{%8,%9},{%0,%1,%2,%3};"
        : "+f"(d[0]), "+f"(d[1]), "+f"(d[2]), "+f"(d[3])
        : "r"(a0), "r"(a1), "r"(a2), "r"(a3), "r"(b0), "r"(b1));
}
__device__ __forceinline__ uint32_t smem_u32(const void* p) {
    return (uint32_t)__cvta_generic_to_shared(p);
}
#define CP16(dst, src) asm volatile("cp.async.cg.shared.global [%0],[%1],16;" :: "r"(dst), "l"(src))
#define CP_COMMIT()    asm volatile("cp.async.commit_group;")
#define CP_WAIT1()     asm volatile("cp.async.wait_group 1;")
#define CP_WAIT0()     asm volatile("cp.async.wait_group 0;")

// ldmatrix: 4 8x8 fp16 tiles
#define LDSM4(r, a)                                                           \
    asm volatile("ldmatrix.sync.aligned.m8n8.x4.shared.b16 {%0,%1,%2,%3},[%4];" \
        : "=r"((r)[0]), "=r"((r)[1]), "=r"((r)[2]), "=r"((r)[3]) : "r"(a))
#define LDSM4T(r, a)                                                          \
    asm volatile("ldmatrix.sync.aligned.m8n8.x4.trans.shared.b16 {%0,%1,%2,%3},[%4];" \
        : "=r"((r)[0]), "=r"((r)[1]), "=r"((r)[2]), "=r"((r)[3]) : "r"(a))

// ---------------------------------------------------------------------------
// Weight fp16 convert (layout preserved, [K,N]): 4 floats/thread
// ---------------------------------------------------------------------------
__global__ void conv_w(const float* __restrict__ src, __half* __restrict__ dst) {
    int i = blockIdx.x * 256 + threadIdx.x;
    float4 v = ((const float4*)src)[i];
    __half2 h0 = __floats2half2_rn(v.x, v.y);
    __half2 h1 = __floats2half2_rn(v.z, v.w);
    uint2 o = {h2_u32(h0), h2_u32(h1)};
    ((uint2*)dst)[i] = o;
}

// ---------------------------------------------------------------------------
// LayerNorm: fp32 in -> fp16 out
// ---------------------------------------------------------------------------
__global__ void ln_kernel(const float* __restrict__ x, const float* __restrict__ g,
                          const float* __restrict__ beta, __half* __restrict__ y) {
    int row = blockIdx.x, t = threadIdx.x;
    const float* xr = x + (size_t)row * DIM_;
    float v0 = xr[t], v1 = xr[t + 256], v2 = xr[t + 512];
    float s = v0 + v1 + v2;
    float q = v0 * v0 + v1 * v1 + v2 * v2;
    __shared__ float rs[8], rq[8];
    #pragma unroll
    for (int o = 16; o; o >>= 1) {
        s += __shfl_xor_sync(0xffffffffu, s, o);
        q += __shfl_xor_sync(0xffffffffu, q, o);
    }
    int lane = t & 31, w = t >> 5;
    if (!lane) { rs[w] = s; rq[w] = q; }
    __syncthreads();
    float S = 0.f, Q = 0.f;
    #pragma unroll
    for (int i = 0; i < 8; ++i) { S += rs[i]; Q += rq[i]; }
    float mean = S * (1.0f / DIM_);
    float var  = Q * (1.0f / DIM_) - mean * mean;
    float inv  = rsqrtf(var + 1e-5f);
    __half* yr = y + (size_t)row * DIM_;
    yr[t]       = __float2half_rn((v0 - mean) * inv * g[t]       + beta[t]);
    yr[t + 256] = __float2half_rn((v1 - mean) * inv * g[t + 256] + beta[t + 256]);
    yr[t + 512] = __float2half_rn((v2 - mean) * inv * g[t + 512] + beta[t + 512]);
}

// ---------------------------------------------------------------------------
// LN of blend: xb = 0.5*(a+b) (written fp32), y = LN(xb) (half)
// ---------------------------------------------------------------------------
__global__ void ln_blend_kernel(const float* __restrict__ a, const float* __restrict__ bsrc,
                                const float* __restrict__ g, const float* __restrict__ beta,
                                __half* __restrict__ y, float* __restrict__ xb) {
    int row = blockIdx.x, t = threadIdx.x;
    const float* ar = a + (size_t)row * DIM_;
    const float* br = bsrc + (size_t)row * DIM_;
    float v0 = 0.5f * (ar[t] + br[t]);
    float v1 = 0.5f * (ar[t + 256] + br[t + 256]);
    float v2 = 0.5f * (ar[t + 512] + br[t + 512]);
    float* xr = xb + (size_t)row * DIM_;
    xr[t] = v0; xr[t + 256] = v1; xr[t + 512] = v2;
    float s = v0 + v1 + v2;
    float q = v0 * v0 + v1 * v1 + v2 * v2;
    __shared__ float rs[8], rq[8];
    #pragma unroll
    for (int o = 16; o; o >>= 1) {
        s += __shfl_xor_sync(0xffffffffu, s, o);
        q += __shfl_xor_sync(0xffffffffu, q, o);
    }
    int lane = t & 31, w = t >> 5;
    if (!lane) { rs[w] = s; rq[w] = q; }
    __syncthreads();
    float S = 0.f, Q = 0.f;
    #pragma unroll
    for (int i = 0; i < 8; ++i) { S += rs[i]; Q += rq[i]; }
    float mean = S * (1.0f / DIM_);
    float var  = Q * (1.0f / DIM_) - mean * mean;
    float inv  = rsqrtf(var + 1e-5f);
    __half* yr = y + (size_t)row * DIM_;
    yr[t]       = __float2half_rn((v0 - mean) * inv * g[t]       + beta[t]);
    yr[t + 256] = __float2half_rn((v1 - mean) * inv * g[t + 256] + beta[t + 256]);
    yr[t + 512] = __float2half_rn((v2 - mean) * inv * g[t + 512] + beta[t + 512]);
}

// ---------------------------------------------------------------------------
// fp16 GEMM: C[M,N] = A[M,K] @ W[K,N] + bias (+res | +gelu)
// A [M,K] half; W [K,N] half (native layout, B fragments via ldmatrix.trans).
// 128x128 tile, BK=32, 256 thr (8 warps 2x4), 3-stage cp.async (dynamic smem).
// EPI: 0 = bias -> half out; 1 = bias+residual -> fp32 out; 2 = bias+gelu -> half out
// ---------------------------------------------------------------------------
#define HST 40     // A smem row stride (halves)
#define BNST 136   // B smem row stride (halves): 272B -> trans-ldmatrix conflict-free
#define GSTG 3
#define A_STAGE (128 * HST)
#define B_STAGE (32 * BNST)
#define GEMM_SMEM ((GSTG * A_STAGE + GSTG * B_STAGE) * 2)   // 56832 B

template<int EPI>
__global__ void __launch_bounds__(256)
gemm_h(const __half* __restrict__ A, const __half* __restrict__ W,
       const float* __restrict__ bias, const float* __restrict__ R,
       void* __restrict__ Cv, int M, int N, int K) {
    extern __shared__ __half sm[];
    __half* As = sm;                        // [GSTG][128][HST]
    __half* Bs = sm + GSTG * A_STAGE;       // [GSTG][32][BNST]
    const int t = threadIdx.x;
    const int w = t >> 5, lane = t & 31, g = lane >> 2, c = lane & 3;
    const int wm = (w >> 2) * 64, wn = (w & 3) * 32;
    const int m0 = blockIdx.y * 128, n0 = blockIdx.x * 128;
    const int NT = K / 32;
    const int lrow = lane & 15;
    const int lcolA = (lane >> 4) * 8;

    auto issue = [&](int kt, int s) {
        __half* Ad = As + s * A_STAGE;
        __half* Bd = Bs + s * B_STAGE;
        #pragma unroll
        for (int i = 0; i < 2; ++i) {
            int li = t + i * 256;
            int arow = li >> 2, ach = li & 3;
            CP16(smem_u32(Ad + arow * HST + ach * 8),
                 A + (size_t)(m0 + arow) * K + kt * 32 + ach * 8);
            int brow = li >> 4, bch = li & 15;
            CP16(smem_u32(Bd + brow * BNST + bch * 8),
                 W + (size_t)(kt * 32 + brow) * N + n0 + bch * 8);
        }
        CP_COMMIT();
    };

    issue(0, 0);
    if (NT > 1) issue(1, 1);
    float acc[4][4][4] = {};
    for (int kt = 0; kt < NT; ++kt) {
        int s = kt % GSTG;
        if (kt + 1 < NT) CP_WAIT1(); else CP_WAIT0();
        __syncthreads();
        const __half* Asb = As + s * A_STAGE;
        const __half* Bsb = Bs + s * B_STAGE;
        #pragma unroll
        for (int ks = 0; ks < 2; ++ks) {
            const int k16 = ks * 16;
            uint32_t af[4][4], bf[2][4];
            #pragma unroll
            for (int mt = 0; mt < 4; ++mt)
                LDSM4(af[mt], smem_u32(Asb + (wm + mt * 16 + lrow) * HST + k16 + lcolA));
            #pragma unroll
            for (int np = 0; np < 2; ++np)
                LDSM4T(bf[np], smem_u32(Bsb + (k16 + lrow) * BNST + wn + np * 16 + lcolA));
            #pragma unroll
            for (int mt = 0; mt < 4; ++mt)
                #pragma unroll
                for (int np = 0; np < 2; ++np) {
                    mma_h(acc[mt][np * 2 + 0], af[mt][0], af[mt][1], af[mt][2], af[mt][3],
                          bf[np][0], bf[np][1]);
                    mma_h(acc[mt][np * 2 + 1], af[mt][0], af[mt][1], af[mt][2], af[mt][3],
                          bf[np][2], bf[np][3]);
                }
        }
        __syncthreads();
        if (kt + 2 < NT) issue(kt + 2, (kt + 2) % GSTG);
    }

    #pragma unroll
    for (int mt = 0; mt < 4; ++mt) {
        #pragma unroll
        for (int nt = 0; nt < 4; ++nt) {
            int row = m0 + wm + mt * 16 + g;
            int col = n0 + wn + nt * 8 + 2 * c;
            float2 bb = *(const float2*)&bias[col];
            #pragma unroll
            for (int hh = 0; hh < 2; ++hh) {
                size_t idx = (size_t)(row + hh * 8) * N + col;
                float v0 = acc[mt][nt][hh * 2 + 0] + bb.x;
                float v1 = acc[mt][nt][hh * 2 + 1] + bb.y;
                if (EPI == 1) {
                    float2 rr = *(const float2*)&R[idx];
                    float2 o = {v0 + rr.x, v1 + rr.y};
                    *(float2*)&((float*)Cv)[idx] = o;
                } else {
                    if (EPI == 2) { v0 = gelu_exact(v0); v1 = gelu_exact(v1); }
                    __half2 o = __halves2half2(__float2half_rn(v0), __float2half_rn(v1));
                    *(__half2*)&((__half*)Cv)[idx] = o;
                }
            }
        }
    }
}

// ---------------------------------------------------------------------------
// Fused attention: scores (fp16 mma) + softmax + attn-map write + PV (fp16 mma).
// Block = 32 q-rows x 1024 keys for one (b,h).
// ---------------------------------------------------------------------------
#define SMST 1036          // Sm row stride (floats); 4144B -> ldmatrix-safe
#define SMSTH (2 * SMST)
#define QST  72
#define SC_SMEM (32*SMST*4 + 32*QST*2 + 2*128*QST*2)   // 174080

__global__ void attn_fused(const __half* __restrict__ qkv, float* __restrict__ S,
                           __half* __restrict__ O) {
    extern __shared__ char smraw[];
    float*  Sm = (float*)smraw;
    __half* SmH = (__half*)smraw;
    __half* Qs = (__half*)(smraw + 32 * SMST * 4);
    __half* KV = Qs + 32 * QST;
    const int t = threadIdx.x;
    const int w = t >> 5, lane = t & 31, g = lane >> 2, c = lane & 3;
    const int bh = blockIdx.y, b = bh / HEADS, h = bh % HEADS;
    const int m0 = blockIdx.x * 32;
    const int wm = (w >> 2) * 16, wn = (w & 3) * 32;
    const __half* Qb = qkv + ((size_t)b * NSEQ + m0) * (3 * DIM_) + h * HDIM;
    const __half* Kb = qkv + ((size_t)b * NSEQ) * (3 * DIM_) + DIM_ + h * HDIM;
    const __half* Vb = qkv + ((size_t)b * NSEQ) * (3 * DIM_) + 2 * DIM_ + h * HDIM;
    const int lrow = lane & 15;
    const int lcolA = (lane >> 4) * 8;
    const int browB = (lane >> 4) * 8 + (lane & 7);
    const int bcolB = lane & 8;

    {
        int row = t >> 3, ch = t & 7;
        CP16(smem_u32(&Qs[row * QST + ch * 8]),
             Qb + (size_t)row * (3 * DIM_) + ch * 8);
        CP_COMMIT();
    }

    auto issueKV = [&](const __half* base, int chn, int buf) {
        __half* Kd = KV + buf * 128 * QST;
        const __half* Kg = base + (size_t)(chn * 128) * (3 * DIM_);
        #pragma unroll
        for (int i = 0; i < 4; ++i) {
            int li = t + i * 256;
            int key = li >> 3, ch = li & 7;
            CP16(smem_u32(&Kd[key * QST + ch * 8]),
                 Kg + (size_t)key * (3 * DIM_) + ch * 8);
        }
        CP_COMMIT();
    };
    issueKV(Kb, 0, 0);
    CP_WAIT0();
    __syncthreads();

    uint32_t aq[4][4];
    #pragma unroll
    for (int ks = 0; ks < 4; ++ks)
        LDSM4(aq[ks], smem_u32(&Qs[(wm + lrow) * QST + ks * 16 + lcolA]));

    // ---- Phase 1: scores ----
    for (int chn = 0; chn < 8; ++chn) {
        int buf = chn & 1;
        if (chn + 1 < 8) { issueKV(Kb, chn + 1, buf ^ 1); CP_WAIT1(); }
        else             { CP_WAIT0(); }
        __syncthreads();
        const __half* Kc = KV + buf * 128 * QST;
        float acc[4][4] = {};
        #pragma unroll
        for (int ks = 0; ks < 4; ++ks) {
            uint32_t bf[2][4];
            #pragma unroll
            for (int np = 0; np < 2; ++np)
                LDSM4(bf[np], smem_u32(&Kc[(wn + np * 16 + browB) * QST + ks * 16 + bcolB]));
            #pragma unroll
            for (int np = 0; np < 2; ++np) {
                mma_h(acc[np * 2 + 0], aq[ks][0], aq[ks][1], aq[ks][2], aq[ks][3],
                      bf[np][0], bf[np][1]);
                mma_h(acc[np * 2 + 1], aq[ks][0], aq[ks][1], aq[ks][2], aq[ks][3],
                      bf[np][2], bf[np][3]);
            }
        }
        const float scl = 0.125f;
        #pragma unroll
        for (int nt = 0; nt < 4; ++nt) {
            int colb = chn * 128 + wn + nt * 8 + 2 * c;
            int row = wm + g;
            float2 o0 = {acc[nt][0] * scl, acc[nt][1] * scl};
            float2 o1 = {acc[nt][2] * scl, acc[nt][3] * scl};
            *(float2*)&Sm[row * SMST + colb]       = o0;
            *(float2*)&Sm[(row + 8) * SMST + colb] = o1;
        }
        __syncthreads();
    }

    issueKV(Vb, 0, 0);
    issueKV(Vb, 1, 1);

    // ---- Phase 2: softmax; fp32 attn map to HBM + half P in place ----
    #pragma unroll
    for (int i = 0; i < 4; ++i) {
        int r = w * 4 + i;
        const float* rowp = Sm + r * SMST;
        __half* hrow = SmH + r * SMSTH;
        float4 v[8];
        float mx = -INFINITY;
        #pragma unroll
        for (int j = 0; j < 8; ++j) {
            v[j] = *(const float4*)(rowp + lane * 4 + j * 128);
            mx = fmaxf(mx, fmaxf(fmaxf(v[j].x, v[j].y), fmaxf(v[j].z, v[j].w)));
        }
        #pragma unroll
        for (int o = 16; o; o >>= 1) mx = fmaxf(mx, __shfl_xor_sync(0xffffffffu, mx, o));
        float s = 0.f;
        #pragma unroll
        for (int j = 0; j < 8; ++j) {
            v[j].x = __expf(v[j].x - mx); v[j].y = __expf(v[j].y - mx);
            v[j].z = __expf(v[j].z - mx); v[j].w = __expf(v[j].w - mx);
            s += v[j].x + v[j].y + v[j].z + v[j].w;
        }
        #pragma unroll
        for (int o = 16; o; o >>= 1) s += __shfl_xor_sync(0xffffffffu, s, o);
        float inv = 1.0f / s;
        float* outp = S + ((size_t)bh * NSEQ + m0 + r) * NSEQ + lane * 4;
        #pragma unroll
        for (int j = 0; j < 8; ++j) {
            float4 o = {v[j].x * inv, v[j].y * inv, v[j].z * inv, v[j].w * inv};
            *(float4*)(outp + j * 128) = o;
            __half2 h0 = __floats2half2_rn(o.x, o.y);
            __half2 h1 = __floats2half2_rn(o.z, o.w);
            uint2 hp = {h2_u32(h0), h2_u32(h1)};
            *(uint2*)(hrow + lane * 4 + j * 128) = hp;
        }
    }

    // ---- Phase 3: PV ----
    const int wm2 = (w >> 2) * 16, wn2 = (w & 3) * 16;
    float acc2[2][4] = {};
    for (int chn = 0; chn < 8; ++chn) {
        int buf = chn & 1;
        if (chn + 2 < 8) CP_WAIT1(); else CP_WAIT0();
        __syncthreads();
        const __half* Vc = KV + buf * 128 * QST;
        #pragma unroll
        for (int ks = 0; ks < 8; ++ks) {
            const int k16 = ks * 16;
            uint32_t pf[4], vf[4];
            LDSM4(pf, smem_u32(&SmH[(wm2 + lrow) * SMSTH + chn * 128 + k16 + lcolA]));
            LDSM4T(vf, smem_u32(&Vc[(k16 + lrow) * QST + wn2 + lcolA]));
            mma_h(acc2[0], pf[0], pf[1], pf[2], pf[3], vf[0], vf[1]);
            mma_h(acc2[1], pf[0], pf[1], pf[2], pf[3], vf[2], vf[3]);
        }
        __syncthreads();
        if (chn + 2 < 8) issueKV(Vb, chn + 2, buf);
    }

    #pragma unroll
    for (int nt = 0; nt < 2; ++nt) {
        int col = wn2 + nt * 8 + 2 * c;
        #pragma unroll
        for (int hh = 0; hh < 2; ++hh) {
            int row = m0 + wm2 + g + hh * 8;
            size_t idx = ((size_t)b * NSEQ + row) * DIM_ + h * HDIM + col;
            __half2 o = __halves2half2(__float2half_rn(acc2[nt][hh * 2 + 0]),
                                       __float2half_rn(acc2[nt][hh * 2 + 1]));
            *(__half2*)&O[idx] = o;
        }
    }
}

// ---------------------------------------------------------------------------
// Host orchestration
// ---------------------------------------------------------------------------
extern "C" void kernel_launch(void* const* d_in, const int* in_sizes, int n_in,
                              void* d_out, int out_size) {
    (void)in_sizes; (void)n_in; (void)out_size;
    const float* x = (const float*)d_in[0];
    const float* prm[24];
    for (int i = 0; i < 24; ++i) prm[i] = (const float*)d_in[1 + i];
    // per-layer: 0 qkv_w, 1 qkv_b, 2 proj_w, 3 proj_b, 4 ln1_g, 5 ln1_b,
    //            6 ln2_g, 7 ln2_b, 8 mlp_w1, 9 mlp_b1, 10 mlp_w2, 11 mlp_b2

    float* out   = (float*)d_out;
    float* attn0 = out + OUT_ELEMS;
    float* attn1 = attn0 + ATTN_ELEMS;

    __half *p_ln, *p_qkv, *p_ao, *p_h, *p_wc;
    float *p_x1, *p_x2, *p_x3;
    cudaGetSymbolAddress((void**)&p_ln,  g_ln);
    cudaGetSymbolAddress((void**)&p_qkv, g_qkv);
    cudaGetSymbolAddress((void**)&p_ao,  g_ao);
    cudaGetSymbolAddress((void**)&p_h,   g_h);
    cudaGetSymbolAddress((void**)&p_x1,  g_x1);
    cudaGetSymbolAddress((void**)&p_x2,  g_x2);
    cudaGetSymbolAddress((void**)&p_x3,  g_x3);
    cudaGetSymbolAddress((void**)&p_wc,  g_wc);

    cudaFuncSetAttribute(attn_fused,
                         cudaFuncAttributeMaxDynamicSharedMemorySize, SC_SMEM);
    cudaFuncSetAttribute(gemm_h<0>, cudaFuncAttributeMaxDynamicSharedMemorySize, GEMM_SMEM);
    cudaFuncSetAttribute(gemm_h<1>, cudaFuncAttributeMaxDynamicSharedMemorySize, GEMM_SMEM);
    cudaFuncSetAttribute(gemm_h<2>, cudaFuncAttributeMaxDynamicSharedMemorySize, GEMM_SMEM);

    dim3 blk(256);

    // fp16 weight conversion ([K,N] layout preserved)
    const int QKV_N = DIM_ * 3 * DIM_;
    const int PRJ_N = DIM_ * DIM_;
    const int W1_N  = DIM_ * MLPH;
    __half* wq[2]; __half* wp[2]; __half* w1[2]; __half* w2[2];
    for (int L = 0; L < 2; ++L) {
        __half* base = p_wc + (size_t)L * WL_STRIDE;
        wq[L] = base;
        wp[L] = base + QKV_N;
        w1[L] = base + QKV_N + PRJ_N;
        w2[L] = base + QKV_N + PRJ_N + W1_N;
        conv_w<<<QKV_N / 1024, blk>>>(prm[L*12 + 0],  wq[L]);
        conv_w<<<PRJ_N / 1024, blk>>>(prm[L*12 + 2],  wp[L]);
        conv_w<<<W1_N  / 1024, blk>>>(prm[L*12 + 8],  w1[L]);
        conv_w<<<W1_N  / 1024, blk>>>(prm[L*12 + 10], w2[L]);
    }

    auto attention = [&](int L, const float* xin, float* attnbuf, float* xout) {
        const float* const* p = prm + L * 12;
        ln_kernel<<<MROWS, blk>>>(xin, p[4], p[5], p_ln);
        gemm_h<0><<<dim3(3 * DIM_ / 128, MROWS / 128), blk, GEMM_SMEM>>>(
            p_ln, wq[L], p[1], nullptr, p_qkv, MROWS, 3 * DIM_, DIM_);
        attn_fused<<<dim3(32, 48), blk, SC_SMEM>>>(p_qkv, attnbuf, p_ao);
        gemm_h<1><<<dim3(DIM_ / 128, MROWS / 128), blk, GEMM_SMEM>>>(
            p_ao, wp[L], p[3], xin, xout, MROWS, DIM_, DIM_);
    };
    auto mlp_tail = [&](int L, const __half* lnin, const float* resid, float* xout) {
        const float* const* p = prm + L * 12;
        gemm_h<2><<<dim3(MLPH / 128, MROWS / 128), blk, GEMM_SMEM>>>(
            lnin, w1[L], p[9], nullptr, p_h, MROWS, MLPH, DIM_);
        gemm_h<1><<<dim3(DIM_ / 128, MROWS / 128), blk, GEMM_SMEM>>>(
            p_h, w2[L], p[11], resid, xout, MROWS, DIM_, MLPH);
    };

    attention(0, x,    attn0, p_x1);
    attention(1, p_x1, attn1, p_x2);
    // mlp layer 1: x3 = x2 + mlp1(ln2_1(x2))
    ln_kernel<<<MROWS, blk>>>(p_x2, prm[12 + 6], prm[12 + 7], p_ln);
    mlp_tail(1, p_ln, p_x2, p_x3);
    // blend + ln fused: xb = 0.5(x1+x3) -> p_x2 ; ln(xb) -> p_ln
    ln_blend_kernel<<<MROWS, blk>>>(p_x1, p_x3, prm[6], prm[7], p_ln, p_x2);
    // mlp layer 0: out = xb + mlp0(ln)
    mlp_tail(0, p_ln, p_x2, out);
}